// round 10
// baseline (speedup 1.0000x reference)
#include <cuda_runtime.h>
#include <cuda_bf16.h>
#include <math.h>
#include <stdint.h>

#define D_EMB 256
#define TT    4096
#define BB    4
#define BT    (BB*TT)          // 16384 rows
#define EPSLN 1e-5f

// ---------------- scratch (static device globals: allocation-free) ----------------
__device__ float g_qkv[3L * BT * D_EMB];             // q,k,v fp32 [3][16384][256]
__device__ float g_scores[(long)BB * TT * TT];       // [4][4096][4096] fp32
__device__ float g_y [BT * D_EMB];                   // attn out
__device__ float g_x1[BT * D_EMB];                   // post-attn residual (fp32 for final)
__device__ float g_y2[BT * D_EMB];                   // ffn out

// bf16 hi/lo split operands for the tensor-core GEMMs
__device__ __nv_bfloat16 g_xs_h [BT * D_EMB],      g_xs_l [BT * D_EMB];       // x split
__device__ __nv_bfloat16 g_qts_h[3 * D_EMB * D_EMB], g_qts_l[3 * D_EMB * D_EMB]; // qkv^T split
__device__ __nv_bfloat16 g_q_h  [BT * D_EMB],      g_q_l  [BT * D_EMB];       // LN(q) split
__device__ __nv_bfloat16 g_k_h  [BT * D_EMB],      g_k_l  [BT * D_EMB];       // LN(k) split
__device__ __nv_bfloat16 g_vts_h[BT * D_EMB],      g_vts_l[BT * D_EMB];       // v^T split
__device__ __nv_bfloat16 g_p_h  [(long)BB * TT * TT], g_p_l[(long)BB * TT * TT]; // softmax split
__device__ __nv_bfloat16 g_x1s_h[BT * D_EMB],      g_x1s_l[BT * D_EMB];       // x1 split
__device__ __nv_bfloat16 g_hs_h [BT * 2 * D_EMB],  g_hs_l [BT * 2 * D_EMB];   // ffn hidden split
__device__ __nv_bfloat16 g_w1s_h[2 * D_EMB * D_EMB], g_w1s_l[2 * D_EMB * D_EMB];
__device__ __nv_bfloat16 g_w2s_h[2 * D_EMB * D_EMB], g_w2s_l[2 * D_EMB * D_EMB];

// ================= helpers (baseline PTX, no 'a' features) =================
__device__ __forceinline__ uint32_t smem_to_u32(const void* p) {
    uint32_t a;
    asm("{ .reg .u64 t; cvta.to.shared.u64 t, %1; cvt.u32.u64 %0, t; }" : "=r"(a) : "l"(p));
    return a;
}
#define LDMX4(r0, r1, r2, r3, addr) \
    asm volatile("ldmatrix.sync.aligned.m8n8.x4.shared.b16 {%0,%1,%2,%3}, [%4];" \
        : "=r"(r0), "=r"(r1), "=r"(r2), "=r"(r3) : "r"(addr))
#define MMA16816(c, a, b0v, b1v) \
    asm volatile("mma.sync.aligned.m16n8k16.row.col.f32.bf16.bf16.f32 " \
        "{%0,%1,%2,%3}, {%4,%5,%6,%7}, {%8,%9}, {%0,%1,%2,%3};" \
        : "+f"((c)[0]), "+f"((c)[1]), "+f"((c)[2]), "+f"((c)[3]) \
        : "r"((a)[0]), "r"((a)[1]), "r"((a)[2]), "r"((a)[3]), "r"(b0v), "r"(b1v))
#define CP_ASYNC16(dst, src) \
    asm volatile("cp.async.ca.shared.global [%0], [%1], 16;" :: "r"(dst), "l"(src) : "memory")
#define CP_COMMIT() asm volatile("cp.async.commit_group;" ::: "memory")
#define CP_WAIT1()  asm volatile("cp.async.wait_group 1;" ::: "memory")
#define CP_WAIT0()  asm volatile("cp.async.wait_group 0;" ::: "memory")

__device__ __forceinline__ void split1(float v, __nv_bfloat16& h, __nv_bfloat16& l) {
    h = __float2bfloat16(v);
    l = __float2bfloat16(v - __bfloat162float(h));
}

// smem: per array 128 rows x 4 chunks(16B) at pitch 5 chunks (80B) -> conflict-free ldmatrix
#define TB   10240                 // 128 * 5 * 16
#define STG  (4 * TB)              // AH, AL, BH, BL
#define GEMM_SMEM (2 * STG)        // double buffered: 81920 B

// prefetch one 128x32 bf16 tile set (A hi/lo + B hi/lo) into stage sbase via cp.async
__device__ __forceinline__ void prefetch(const __nv_bfloat16* Ah, const __nv_bfloat16* Al,
                                         const __nv_bfloat16* Bh, const __nv_bfloat16* Bl,
                                         int K, int kt, uint32_t sbase, int tid)
{
    const int r  = tid >> 1;
    const int cp = (tid & 1) * 2;                       // chunk pair {0,1} or {2,3}
    const long go = (long)r * K + kt * 32 + cp * 8;     // bf16 elems
    const uint32_t so = sbase + (uint32_t)((r * 5 + cp) * 16);
    CP_ASYNC16(so,              Ah + go);
    CP_ASYNC16(so + 16,         Ah + go + 8);
    CP_ASYNC16(so + TB,         Al + go);
    CP_ASYNC16(so + TB + 16,    Al + go + 8);
    CP_ASYNC16(so + 2*TB,       Bh + go);
    CP_ASYNC16(so + 2*TB + 16,  Bh + go + 8);
    CP_ASYNC16(so + 3*TB,       Bl + go);
    CP_ASYNC16(so + 3*TB + 16,  Bl + go + 8);
}

// ---------------- pipelined tensor-core GEMM ----------------
// C[M,N] = epi(alpha * (A_h+A_l)[M,K] @ (B_h+B_l)[N,K]^T), 3-product fp32 emulation.
// epi: 0 = none (fp32 C), 1 = leaky (fp32 C), 2 = leaky + write bf16 split (Ch, Cl)
__global__ __launch_bounds__(256, 2)
void gemm_tc(const __nv_bfloat16* __restrict__ Ah, const __nv_bfloat16* __restrict__ Al,
             const __nv_bfloat16* __restrict__ Bh, const __nv_bfloat16* __restrict__ Bl,
             float* __restrict__ C, __nv_bfloat16* __restrict__ Ch, __nv_bfloat16* __restrict__ Cl,
             int K, int N, long sA, long sB, long sC, float alpha, int epi)
{
    extern __shared__ char sm[];
    const uint32_t smb = smem_to_u32(sm);
    const int tid  = threadIdx.x;
    const int wid  = tid >> 5;
    const int lane = tid & 31;

    Ah += blockIdx.z * sA;  Al += blockIdx.z * sA;
    Bh += blockIdx.z * sB;  Bl += blockIdx.z * sB;
    const int row0 = blockIdx.y * 128;
    const int col0 = blockIdx.x * 128;

    const int m0w = (wid & 3) * 32;
    const int n0w = (wid >> 2) * 64;

    float acc[2][8][4];
#pragma unroll
    for (int m = 0; m < 2; m++)
#pragma unroll
        for (int n = 0; n < 8; n++)
#pragma unroll
            for (int j = 0; j < 4; j++) acc[m][n][j] = 0.f;

    const __nv_bfloat16* Abh = Ah + (long)row0 * K;
    const __nv_bfloat16* Abl = Al + (long)row0 * K;
    const __nv_bfloat16* Bbh = Bh + (long)col0 * K;
    const __nv_bfloat16* Bbl = Bl + (long)col0 * K;
    const int KT = K >> 5;

    // per-lane ldmatrix row bases (same fragment mapping as the passing R8 kernel)
    const uint32_t a_row = (uint32_t)((m0w + (lane & 15)) * 80) + ((lane & 16) ? 16u : 0u);
    const uint32_t b_row = (uint32_t)((n0w + (lane & 7) + ((lane & 16) >> 1)) * 80)
                         + ((lane & 8) ? 16u : 0u);

    prefetch(Abh, Abl, Bbh, Bbl, K, 0, smb, tid);
    CP_COMMIT();

    for (int kt = 0; kt < KT; kt++) {
        if (kt + 1 < KT) {
            prefetch(Abh, Abl, Bbh, Bbl, K, kt + 1, smb + ((kt + 1) & 1) * STG, tid);
            CP_COMMIT();
            CP_WAIT1();
        } else {
            CP_WAIT0();
        }
        __syncthreads();

        const uint32_t sb = smb + (kt & 1) * STG;
#pragma unroll
        for (int kb = 0; kb < 2; kb++) {
            const uint32_t kofs = (uint32_t)(kb * 32);
            uint32_t ah[2][4], al[2][4];
#pragma unroll
            for (int m = 0; m < 2; m++) {
                uint32_t aa = sb + a_row + (uint32_t)(m * 16 * 80) + kofs;
                LDMX4(ah[m][0], ah[m][1], ah[m][2], ah[m][3], aa);
                LDMX4(al[m][0], al[m][1], al[m][2], al[m][3], aa + TB);
            }
#pragma unroll
            for (int np = 0; np < 4; np++) {
                uint32_t ba = sb + 2 * TB + b_row + (uint32_t)(np * 16 * 80) + kofs;
                uint32_t bh[4], bl[4];
                LDMX4(bh[0], bh[1], bh[2], bh[3], ba);
                LDMX4(bl[0], bl[1], bl[2], bl[3], ba + TB);
#pragma unroll
                for (int m = 0; m < 2; m++) {
                    MMA16816(acc[m][np*2],   ah[m], bh[0], bh[1]);
                    MMA16816(acc[m][np*2],   al[m], bh[0], bh[1]);
                    MMA16816(acc[m][np*2],   ah[m], bl[0], bl[1]);
                    MMA16816(acc[m][np*2+1], ah[m], bh[2], bh[3]);
                    MMA16816(acc[m][np*2+1], al[m], bh[2], bh[3]);
                    MMA16816(acc[m][np*2+1], ah[m], bl[2], bl[3]);
                }
            }
        }
        __syncthreads();
    }

    // epilogue
    C  += blockIdx.z * sC;
    Ch += blockIdx.z * sC;  Cl += blockIdx.z * sC;
#pragma unroll
    for (int m = 0; m < 2; m++) {
        const long r0 = row0 + m0w + m * 16 + (lane >> 2);
#pragma unroll
        for (int nb = 0; nb < 8; nb++) {
            const int cc = col0 + n0w + nb * 8 + (lane & 3) * 2;
            float v[4];
            v[0] = alpha * acc[m][nb][0];  v[1] = alpha * acc[m][nb][1];
            v[2] = alpha * acc[m][nb][2];  v[3] = alpha * acc[m][nb][3];
            if (epi >= 1) {
#pragma unroll
                for (int j = 0; j < 4; j++) v[j] = v[j] > 0.f ? v[j] : 0.2f * v[j];
            }
            if (epi == 2) {
                __nv_bfloat16 h0, l0, h1, l1;
                split1(v[0], h0, l0); split1(v[1], h1, l1);
                *(__nv_bfloat162*)(Ch + r0 * N + cc) = __nv_bfloat162(h0, h1);
                *(__nv_bfloat162*)(Cl + r0 * N + cc) = __nv_bfloat162(l0, l1);
                split1(v[2], h0, l0); split1(v[3], h1, l1);
                *(__nv_bfloat162*)(Ch + (r0 + 8) * N + cc) = __nv_bfloat162(h0, h1);
                *(__nv_bfloat162*)(Cl + (r0 + 8) * N + cc) = __nv_bfloat162(l0, l1);
            } else {
                *(float2*)(C + r0 * N + cc)       = make_float2(v[0], v[1]);
                *(float2*)(C + (r0 + 8) * N + cc) = make_float2(v[2], v[3]);
            }
        }
    }
}

// ---------------- elementwise split: fp32 -> bf16 hi/lo (2 elems/thread) ----------------
__global__ __launch_bounds__(256)
void split2(const float* __restrict__ in, __nv_bfloat16* __restrict__ oh,
            __nv_bfloat16* __restrict__ ol)
{
    const long i = (long)blockIdx.x * 256 + threadIdx.x;
    float2 v = ((const float2*)in)[i];
    __nv_bfloat16 h0, l0, h1, l1;
    split1(v.x, h0, l0); split1(v.y, h1, l1);
    ((__nv_bfloat162*)oh)[i] = __nv_bfloat162(h0, h1);
    ((__nv_bfloat162*)ol)[i] = __nv_bfloat162(l0, l1);
}

// ---------------- tiled transpose + split: out[c][r] = split(in[r][c]) ----------------
__global__ __launch_bounds__(256)
void transpose_split(const float* __restrict__ in,
                     __nv_bfloat16* __restrict__ oh, __nv_bfloat16* __restrict__ ol,
                     int rows, int cols, long sIn, long sOut)
{
    __shared__ float t[32][33];
    in += (long)blockIdx.z * sIn;
    oh += (long)blockIdx.z * sOut;  ol += (long)blockIdx.z * sOut;
    const int c0 = blockIdx.x * 32, r0 = blockIdx.y * 32;
    const int tx = threadIdx.x & 31, ty = threadIdx.x >> 5;
#pragma unroll
    for (int i = 0; i < 32; i += 8)
        t[ty + i][tx] = in[(long)(r0 + ty + i) * cols + c0 + tx];
    __syncthreads();
#pragma unroll
    for (int i = 0; i < 32; i += 8) {
        __nv_bfloat16 h, l;
        split1(t[tx][ty + i], h, l);
        const long o = (long)(c0 + ty + i) * rows + r0 + tx;
        oh[o] = h;  ol[o] = l;
    }
}

// ---------------- row softmax over T=4096 -> bf16 hi/lo P ----------------
__device__ __forceinline__ float warp_red_max(float v) {
#pragma unroll
    for (int o = 16; o; o >>= 1) v = fmaxf(v, __shfl_xor_sync(0xffffffffu, v, o));
    return v;
}
__device__ __forceinline__ float warp_red_sum(float v) {
#pragma unroll
    for (int o = 16; o; o >>= 1) v += __shfl_xor_sync(0xffffffffu, v, o);
    return v;
}

__global__ __launch_bounds__(256)
void softmax_rows(const float* __restrict__ S,
                  __nv_bfloat16* __restrict__ ph, __nv_bfloat16* __restrict__ pl)
{
    const long row = blockIdx.x;
    const float* p = S + row * TT;
    __nv_bfloat16* oph = ph + row * TT;
    __nv_bfloat16* opl = pl + row * TT;
    const int tid = threadIdx.x;
    __shared__ float red[8];

    float v[16];
#pragma unroll
    for (int j = 0; j < 16; j++) v[j] = p[tid + j * 256];

    float m = -3.4e38f;
#pragma unroll
    for (int j = 0; j < 16; j++) m = fmaxf(m, v[j]);
    m = warp_red_max(m);
    if ((tid & 31) == 0) red[tid >> 5] = m;
    __syncthreads();
    m = red[0];
#pragma unroll
    for (int i = 1; i < 8; i++) m = fmaxf(m, red[i]);
    __syncthreads();

    float s = 0.f;
#pragma unroll
    for (int j = 0; j < 16; j++) { v[j] = __expf(v[j] - m); s += v[j]; }
    s = warp_red_sum(s);
    if ((tid & 31) == 0) red[tid >> 5] = s;
    __syncthreads();
    s = 0.f;
#pragma unroll
    for (int i = 0; i < 8; i++) s += red[i];
    const float inv = 1.f / s;
#pragma unroll
    for (int j = 0; j < 16; j++) {
        __nv_bfloat16 h, l;
        split1(v[j] * inv, h, l);
        oph[tid + j * 256] = h;
        opl[tid + j * 256] = l;
    }
}

// ---------------- warp-per-row LayerNorm (D=256, 8 elems/lane) ----------------
__device__ __forceinline__ void ln_row(const float* __restrict__ in,
                                       float v[8], int lane,
                                       const float* __restrict__ w,
                                       const float* __restrict__ b)
{
#pragma unroll
    for (int j = 0; j < 8; j++) v[j] = in[lane + j * 32];
    float s = 0.f;
#pragma unroll
    for (int j = 0; j < 8; j++) s += v[j];
    const float mean = warp_red_sum(s) * (1.f / 256.f);
    float q = 0.f;
#pragma unroll
    for (int j = 0; j < 8; j++) { float d = v[j] - mean; q += d * d; }
    const float rstd = rsqrtf(warp_red_sum(q) * (1.f / 256.f) + EPSLN);
#pragma unroll
    for (int j = 0; j < 8; j++) {
        const int e = lane + j * 32;
        v[j] = (v[j] - mean) * rstd * w[e] + b[e];
    }
}

// LN(q), LN(k) -> bf16 split arrays
__global__ __launch_bounds__(256)
void ln_qk(const float* __restrict__ wq, const float* __restrict__ bq,
           const float* __restrict__ wk, const float* __restrict__ bk,
           __nv_bfloat16* __restrict__ qh, __nv_bfloat16* __restrict__ ql,
           __nv_bfloat16* __restrict__ kh, __nv_bfloat16* __restrict__ kl)
{
    const int tensor = blockIdx.y;
    const float* base = g_qkv + (long)tensor * BT * D_EMB;
    const float* w = tensor ? wk : wq;
    const float* b = tensor ? bk : bq;
    __nv_bfloat16* oh = tensor ? kh : qh;
    __nv_bfloat16* ol = tensor ? kl : ql;
    const long row = (long)blockIdx.x * 8 + (threadIdx.x >> 5);
    const int lane = threadIdx.x & 31;
    float v[8];
    ln_row(base + row * D_EMB, v, lane, w, b);
#pragma unroll
    for (int j = 0; j < 8; j++) {
        __nv_bfloat16 h, l;
        split1(v[j], h, l);
        oh[row * D_EMB + lane + j * 32] = h;
        ol[row * D_EMB + lane + j * 32] = l;
    }
}

// x1 = 0.7 * (x + LN(y));  writes fp32 + bf16 split
__global__ __launch_bounds__(256)
void attn_ln_res(const float* __restrict__ x,
                 const float* __restrict__ w, const float* __restrict__ b,
                 __nv_bfloat16* __restrict__ oh, __nv_bfloat16* __restrict__ ol)
{
    const long row = (long)blockIdx.x * 8 + (threadIdx.x >> 5);
    const int lane = threadIdx.x & 31;
    float v[8];
    ln_row(g_y + row * D_EMB, v, lane, w, b);
#pragma unroll
    for (int j = 0; j < 8; j++) {
        const long e = row * D_EMB + lane + j * 32;
        const float r = 0.7f * (x[e] + v[j]);
        g_x1[e] = r;
        __nv_bfloat16 h, l;
        split1(r, h, l);
        oh[e] = h;  ol[e] = l;
    }
}

// out = 0.7 * (x1 + LN(y2))
__global__ __launch_bounds__(256)
void ff_ln_res(float* __restrict__ out,
               const float* __restrict__ w, const float* __restrict__ b)
{
    const long row = (long)blockIdx.x * 8 + (threadIdx.x >> 5);
    const int lane = threadIdx.x & 31;
    float v[8];
    ln_row(g_y2 + row * D_EMB, v, lane, w, b);
#pragma unroll
    for (int j = 0; j < 8; j++) {
        const long e = row * D_EMB + lane + j * 32;
        out[e] = 0.7f * (g_x1[e] + v[j]);
    }
}

// ---------------- launch ----------------
extern "C" void kernel_launch(void* const* d_in, const int* in_sizes, int n_in,
                              void* d_out, int out_size)
{
    const float* x      = (const float*)d_in[0];
    const float* qkvw   = (const float*)d_in[1];
    const float* ln_q_w = (const float*)d_in[2];
    const float* ln_q_b = (const float*)d_in[3];
    const float* ln_k_w = (const float*)d_in[4];
    const float* ln_k_b = (const float*)d_in[5];
    const float* ln_a_w = (const float*)d_in[6];
    const float* ln_a_b = (const float*)d_in[7];
    const float* w1     = (const float*)d_in[8];
    const float* w2     = (const float*)d_in[9];
    const float* ln_f_w = (const float*)d_in[10];
    const float* ln_f_b = (const float*)d_in[11];
    float* out = (float*)d_out;

    float *p_qkv, *p_scores, *p_y2;
    __nv_bfloat16 *xs_h, *xs_l, *qts_h, *qts_l, *q_h, *q_l, *k_h, *k_l;
    __nv_bfloat16 *vts_h, *vts_l, *p_h, *p_l, *x1s_h, *x1s_l, *hs_h, *hs_l;
    __nv_bfloat16 *w1s_h, *w1s_l, *w2s_h, *w2s_l;
    float *p_y;
    cudaGetSymbolAddress((void**)&p_qkv,    g_qkv);
    cudaGetSymbolAddress((void**)&p_scores, g_scores);
    cudaGetSymbolAddress((void**)&p_y,      g_y);
    cudaGetSymbolAddress((void**)&p_y2,     g_y2);
    cudaGetSymbolAddress((void**)&xs_h,  g_xs_h);   cudaGetSymbolAddress((void**)&xs_l,  g_xs_l);
    cudaGetSymbolAddress((void**)&qts_h, g_qts_h);  cudaGetSymbolAddress((void**)&qts_l, g_qts_l);
    cudaGetSymbolAddress((void**)&q_h,   g_q_h);    cudaGetSymbolAddress((void**)&q_l,   g_q_l);
    cudaGetSymbolAddress((void**)&k_h,   g_k_h);    cudaGetSymbolAddress((void**)&k_l,   g_k_l);
    cudaGetSymbolAddress((void**)&vts_h, g_vts_h);  cudaGetSymbolAddress((void**)&vts_l, g_vts_l);
    cudaGetSymbolAddress((void**)&p_h,   g_p_h);    cudaGetSymbolAddress((void**)&p_l,   g_p_l);
    cudaGetSymbolAddress((void**)&x1s_h, g_x1s_h);  cudaGetSymbolAddress((void**)&x1s_l, g_x1s_l);
    cudaGetSymbolAddress((void**)&hs_h,  g_hs_h);   cudaGetSymbolAddress((void**)&hs_l,  g_hs_l);
    cudaGetSymbolAddress((void**)&w1s_h, g_w1s_h);  cudaGetSymbolAddress((void**)&w1s_l, g_w1s_l);
    cudaGetSymbolAddress((void**)&w2s_h, g_w2s_h);  cudaGetSymbolAddress((void**)&w2s_l, g_w2s_l);

    cudaFuncSetAttribute(gemm_tc, cudaFuncAttributeMaxDynamicSharedMemorySize, GEMM_SMEM);

    // 0) splits of inputs (independent)
    split2<<<BT * D_EMB / 512, 256>>>(x, xs_h, xs_l);
    split2<<<2 * D_EMB * D_EMB / 512, 256>>>(w1, w1s_h, w1s_l);
    split2<<<2 * D_EMB * D_EMB / 512, 256>>>(w2, w2s_h, w2s_l);
    // qkv weights: [3][d][D] -> [3][D][d] split (NT form)
    transpose_split<<<dim3(8, 8, 3), 256>>>(qkvw, qts_h, qts_l, 256, 256,
                                            (long)D_EMB * D_EMB, (long)D_EMB * D_EMB);

    // 1) q,k,v = x @ qkvT^T   M=16384, N=256, K=256 (fp32 out)
    gemm_tc<<<dim3(2, 128, 3), 256, GEMM_SMEM>>>(
        xs_h, xs_l, qts_h, qts_l, p_qkv, nullptr, nullptr,
        D_EMB, D_EMB, 0L, (long)D_EMB * D_EMB, (long)BT * D_EMB, 1.f, 0);

    // 2) v^T split per batch: [4096][256] -> [256][4096]
    transpose_split<<<dim3(8, 128, BB), 256>>>(p_qkv + 2L * BT * D_EMB, vts_h, vts_l,
                                               TT, D_EMB, (long)TT * D_EMB, (long)TT * D_EMB);

    // 3) LN(q), LN(k) -> split
    ln_qk<<<dim3(BT / 8, 2), 256>>>(ln_q_w, ln_q_b, ln_k_w, ln_k_b, q_h, q_l, k_h, k_l);

    // 4) scores = q @ k^T / 16   M=N=4096, K=256 per batch
    gemm_tc<<<dim3(32, 32, BB), 256, GEMM_SMEM>>>(
        q_h, q_l, k_h, k_l, p_scores, nullptr, nullptr,
        D_EMB, TT, (long)TT * D_EMB, (long)TT * D_EMB, (long)TT * TT, 1.f / 16.f, 0);

    // 5) softmax rows -> P split
    softmax_rows<<<BB * TT, 256>>>(p_scores, p_h, p_l);

    // 6) y = P @ vT^T   M=4096, N=256, K=4096 per batch
    gemm_tc<<<dim3(2, 32, BB), 256, GEMM_SMEM>>>(
        p_h, p_l, vts_h, vts_l, p_y, nullptr, nullptr,
        TT, D_EMB, (long)TT * TT, (long)D_EMB * TT, (long)TT * D_EMB, 1.f, 0);

    // 7) x1 = 0.7*(x + LN(y)) -> fp32 + split
    attn_ln_res<<<BT / 8, 256>>>(x, ln_a_w, ln_a_b, x1s_h, x1s_l);

    // 8) h = leaky(x1 @ w1^T) -> bf16 split  M=16384, N=512, K=256
    gemm_tc<<<dim3(4, 128, 1), 256, GEMM_SMEM>>>(
        x1s_h, x1s_l, w1s_h, w1s_l, nullptr, hs_h, hs_l,
        D_EMB, 2 * D_EMB, 0L, 0L, 0L, 1.f, 2);

    // 9) y2 = leaky(h @ w2^T)   M=16384, N=256, K=512 (fp32 out)
    gemm_tc<<<dim3(2, 128, 1), 256, GEMM_SMEM>>>(
        hs_h, hs_l, w2s_h, w2s_l, p_y2, nullptr, nullptr,
        2 * D_EMB, D_EMB, 0L, 0L, 0L, 1.f, 1);

    // 10) out = 0.7 * (x1 + LN(y2))
    ff_ln_res<<<BT / 8, 256>>>(out, ln_f_w, ln_f_b);
}

// round 11
// speedup vs baseline: 1.0340x; 1.0340x over previous
#include <cuda_runtime.h>
#include <cuda_bf16.h>
#include <math.h>
#include <stdint.h>

#define D_EMB 256
#define TT    4096
#define BB    4
#define BT    (BB*TT)          // 16384 rows
#define EPSLN 1e-5f

// ---------------- scratch (static device globals: allocation-free) ----------------
__device__ float  g_qkv[3L * BT * D_EMB];            // q,k,v fp32
__device__ float  g_scores[(long)BB * TT * TT];      // scaled scores S
__device__ float2 g_stat[(long)BB * TT];             // (rowmax, 1/sumexp)
__device__ float  g_y [BT * D_EMB];                  // attn out
__device__ float  g_x1[BT * D_EMB];                  // post-attn residual
__device__ float  g_y2[BT * D_EMB];                  // ffn out

// bf16 hi/lo split operands
__device__ __nv_bfloat16 g_xs_h [BT * D_EMB],        g_xs_l [BT * D_EMB];
__device__ __nv_bfloat16 g_qts_h[3 * D_EMB * D_EMB], g_qts_l[3 * D_EMB * D_EMB];
__device__ __nv_bfloat16 g_q_h  [BT * D_EMB],        g_q_l  [BT * D_EMB];
__device__ __nv_bfloat16 g_k_h  [BT * D_EMB],        g_k_l  [BT * D_EMB];
__device__ __nv_bfloat16 g_vts_h[BT * D_EMB],        g_vts_l[BT * D_EMB];
__device__ __nv_bfloat16 g_x1s_h[BT * D_EMB],        g_x1s_l[BT * D_EMB];
__device__ __nv_bfloat16 g_hs_h [BT * 2 * D_EMB],    g_hs_l [BT * 2 * D_EMB];
__device__ __nv_bfloat16 g_w1s_h[2 * D_EMB * D_EMB], g_w1s_l[2 * D_EMB * D_EMB];
__device__ __nv_bfloat16 g_w2s_h[2 * D_EMB * D_EMB], g_w2s_l[2 * D_EMB * D_EMB];

// ================= helpers (baseline PTX, no 'a' features) =================
__device__ __forceinline__ uint32_t smem_to_u32(const void* p) {
    uint32_t a;
    asm("{ .reg .u64 t; cvta.to.shared.u64 t, %1; cvt.u32.u64 %0, t; }" : "=r"(a) : "l"(p));
    return a;
}
#define LDMX4(r0, r1, r2, r3, addr) \
    asm volatile("ldmatrix.sync.aligned.m8n8.x4.shared.b16 {%0,%1,%2,%3}, [%4];" \
        : "=r"(r0), "=r"(r1), "=r"(r2), "=r"(r3) : "r"(addr))
#define MMA16816(c, a, b0v, b1v) \
    asm volatile("mma.sync.aligned.m16n8k16.row.col.f32.bf16.bf16.f32 " \
        "{%0,%1,%2,%3}, {%4,%5,%6,%7}, {%8,%9}, {%0,%1,%2,%3};" \
        : "+f"((c)[0]), "+f"((c)[1]), "+f"((c)[2]), "+f"((c)[3]) \
        : "r"((a)[0]), "r"((a)[1]), "r"((a)[2]), "r"((a)[3]), "r"(b0v), "r"(b1v))

__device__ __forceinline__ void split1(float v, __nv_bfloat16& h, __nv_bfloat16& l) {
    h = __float2bfloat16(v);
    l = __float2bfloat16(v - __bfloat162float(h));
}

// smem tile: 128 rows x 64 bf16, row pitch 144 B (R8-proven ldmatrix layout)
#define TPITCH 144
#define TB     (128 * TPITCH)        // 18432
#define GEMM_SMEM (4 * TB)           // AH, AL, BH, BL: 73728

// copy one 128x64 bf16 tile (pre-split source) into smem; NT threads cooperate
__device__ __forceinline__ void load_bf16_tile(const __nv_bfloat16* __restrict__ g, int ld,
                                               char* sm, int off, int tid, int NT)
{
    const int per = 1024 / NT;     // 16B chunks per thread (NT=256 -> 4, 512 -> 2)
#pragma unroll
    for (int i = 0; i < 4; i++) {
        if (i >= per) break;
        int idx = tid + i * NT;
        int r  = idx >> 3;
        int ch = idx & 7;
        *(uint4*)(sm + off + r * TPITCH + ch * 16) =
            *(const uint4*)(g + (long)r * ld + ch * 8);
    }
}

// ---------------- generic 256-thread GEMM (R8 engine, bf16-copy loads) ----------------
// C[M,N] = epi(alpha * (Ah+Al)[M,K] @ (Bh+Bl)[N,K]^T), 3-product fp32 emulation
// epi: 0 none (fp32 C), 1 leaky (fp32 C), 2 leaky + bf16 split out (Ch, Cl)
__global__ __launch_bounds__(256, 2)
void gemm_tc(const __nv_bfloat16* __restrict__ Ah, const __nv_bfloat16* __restrict__ Al,
             const __nv_bfloat16* __restrict__ Bh, const __nv_bfloat16* __restrict__ Bl,
             float* __restrict__ C, __nv_bfloat16* __restrict__ Ch, __nv_bfloat16* __restrict__ Cl,
             int K, int N, long sA, long sB, long sC, float alpha, int epi)
{
    extern __shared__ char sm[];
    const uint32_t smb = smem_to_u32(sm);
    const int tid  = threadIdx.x;
    const int wid  = tid >> 5;
    const int lane = tid & 31;

    Ah += blockIdx.z * sA;  Al += blockIdx.z * sA;
    Bh += blockIdx.z * sB;  Bl += blockIdx.z * sB;
    const int row0 = blockIdx.y * 128;
    const int col0 = blockIdx.x * 128;

    const int m0w = (wid & 3) * 32;
    const int n0w = (wid >> 2) * 64;

    float acc[2][8][4];
#pragma unroll
    for (int m = 0; m < 2; m++)
#pragma unroll
        for (int n = 0; n < 8; n++)
#pragma unroll
            for (int j = 0; j < 4; j++) acc[m][n][j] = 0.f;

    const uint32_t a_row = (uint32_t)((m0w + (lane & 15)) * TPITCH) + ((lane & 16) ? 16u : 0u);
    const uint32_t b_row = (uint32_t)((n0w + (lane & 7) + ((lane & 16) >> 1)) * TPITCH)
                         + ((lane & 8) ? 16u : 0u);

    const int KT = K >> 6;
    for (int kt = 0; kt < KT; kt++) {
        if (kt) __syncthreads();
        const long ko = (long)kt * 64;
        load_bf16_tile(Ah + (long)row0 * K + ko, K, sm, 0,      tid, 256);
        load_bf16_tile(Al + (long)row0 * K + ko, K, sm, TB,     tid, 256);
        load_bf16_tile(Bh + (long)col0 * K + ko, K, sm, 2 * TB, tid, 256);
        load_bf16_tile(Bl + (long)col0 * K + ko, K, sm, 3 * TB, tid, 256);
        __syncthreads();

#pragma unroll
        for (int k16 = 0; k16 < 4; k16++) {
            const uint32_t kb = (uint32_t)(k16 * 32);
            uint32_t ah[2][4], al[2][4];
#pragma unroll
            for (int m = 0; m < 2; m++) {
                uint32_t aa = smb + a_row + (uint32_t)(m * 16 * TPITCH) + kb;
                LDMX4(ah[m][0], ah[m][1], ah[m][2], ah[m][3], aa);
                LDMX4(al[m][0], al[m][1], al[m][2], al[m][3], aa + TB);
            }
#pragma unroll
            for (int np = 0; np < 4; np++) {
                uint32_t ba = smb + 2 * TB + b_row + (uint32_t)(np * 16 * TPITCH) + kb;
                uint32_t bh[4], bl[4];
                LDMX4(bh[0], bh[1], bh[2], bh[3], ba);
                LDMX4(bl[0], bl[1], bl[2], bl[3], ba + TB);
#pragma unroll
                for (int m = 0; m < 2; m++) {
                    MMA16816(acc[m][np*2],   ah[m], bh[0], bh[1]);
                    MMA16816(acc[m][np*2],   al[m], bh[0], bh[1]);
                    MMA16816(acc[m][np*2],   ah[m], bl[0], bl[1]);
                    MMA16816(acc[m][np*2+1], ah[m], bh[2], bh[3]);
                    MMA16816(acc[m][np*2+1], al[m], bh[2], bh[3]);
                    MMA16816(acc[m][np*2+1], ah[m], bl[2], bl[3]);
                }
            }
        }
    }

    C  += blockIdx.z * sC;
    Ch += blockIdx.z * sC;  Cl += blockIdx.z * sC;
#pragma unroll
    for (int m = 0; m < 2; m++) {
        const long r0 = row0 + m0w + m * 16 + (lane >> 2);
#pragma unroll
        for (int nb = 0; nb < 8; nb++) {
            const int cc = col0 + n0w + nb * 8 + (lane & 3) * 2;
            float v[4];
            v[0] = alpha * acc[m][nb][0];  v[1] = alpha * acc[m][nb][1];
            v[2] = alpha * acc[m][nb][2];  v[3] = alpha * acc[m][nb][3];
            if (epi >= 1) {
#pragma unroll
                for (int j = 0; j < 4; j++) v[j] = v[j] > 0.f ? v[j] : 0.2f * v[j];
            }
            if (epi == 2) {
                __nv_bfloat16 h0, l0, h1, l1;
                split1(v[0], h0, l0); split1(v[1], h1, l1);
                *(__nv_bfloat162*)(Ch + r0 * N + cc) = __nv_bfloat162(h0, h1);
                *(__nv_bfloat162*)(Cl + r0 * N + cc) = __nv_bfloat162(l0, l1);
                split1(v[2], h0, l0); split1(v[3], h1, l1);
                *(__nv_bfloat162*)(Ch + (r0 + 8) * N + cc) = __nv_bfloat162(h0, h1);
                *(__nv_bfloat162*)(Cl + (r0 + 8) * N + cc) = __nv_bfloat162(l0, l1);
            } else {
                *(float2*)(C + r0 * N + cc)       = make_float2(v[0], v[1]);
                *(float2*)(C + (r0 + 8) * N + cc) = make_float2(v[2], v[3]);
            }
        }
    }
}

// ---------------- PV GEMM: y = softmax(S) @ V, P materialized only in smem ----------------
// 512 threads, tile 128(t) x 256(d) full-N: each S element read exactly once.
// A tile: S fp32 -> p = expf(s - m) * inv -> bf16 hi/lo.  B: pre-split vT copy.
#define PV_BTB (256 * TPITCH)              // B tile: 256 rows -> 36864
#define PV_SMEM (2 * TB + 2 * PV_BTB)      // 110592
__global__ __launch_bounds__(512, 1)
void gemm_pv(const float* __restrict__ S, const float2* __restrict__ stat,
             const __nv_bfloat16* __restrict__ Bh, const __nv_bfloat16* __restrict__ Bl,
             float* __restrict__ C)
{
    extern __shared__ char sm[];
    const uint32_t smb = smem_to_u32(sm);
    const int tid  = threadIdx.x;
    const int wid  = tid >> 5;
    const int lane = tid & 31;

    S    += (long)blockIdx.z * TT * TT;
    stat += (long)blockIdx.z * TT;
    Bh   += (long)blockIdx.z * D_EMB * TT;
    Bl   += (long)blockIdx.z * D_EMB * TT;
    C    += (long)blockIdx.z * TT * D_EMB;
    const int row0 = blockIdx.y * 128;

    const int m0w = (wid & 3) * 32;
    const int n0w = (wid >> 2) * 64;          // 0..192

    float acc[2][8][4];
#pragma unroll
    for (int m = 0; m < 2; m++)
#pragma unroll
        for (int n = 0; n < 8; n++)
#pragma unroll
            for (int j = 0; j < 4; j++) acc[m][n][j] = 0.f;

    const uint32_t a_row = (uint32_t)((m0w + (lane & 15)) * TPITCH) + ((lane & 16) ? 16u : 0u);
    const uint32_t b_row = (uint32_t)((n0w + (lane & 7) + ((lane & 16) >> 1)) * TPITCH)
                         + ((lane & 8) ? 16u : 0u);

    for (int kt = 0; kt < TT / 64; kt++) {
        if (kt) __syncthreads();
        // A: 1024 chunks / 512 thr = 2 each; fp32 S -> exp -> split
#pragma unroll
        for (int i = 0; i < 2; i++) {
            int idx = tid + i * 512;
            int r  = idx >> 3;
            int ch = idx & 7;
            const float* p = S + (long)(row0 + r) * TT + kt * 64 + ch * 8;
            float2 st = stat[row0 + r];       // (m, inv)
            float4 f0 = *(const float4*)p;
            float4 f1 = *(const float4*)(p + 4);
            float f[8] = {f0.x, f0.y, f0.z, f0.w, f1.x, f1.y, f1.z, f1.w};
            unsigned int hi[4], lo[4];
#pragma unroll
            for (int j = 0; j < 4; j++) {
                float p0 = __expf(f[2*j]   - st.x) * st.y;
                float p1 = __expf(f[2*j+1] - st.x) * st.y;
                __nv_bfloat16 h0, l0, h1, l1;
                split1(p0, h0, l0); split1(p1, h1, l1);
                __nv_bfloat162 hh(h0, h1), ll(l0, l1);
                hi[j] = *(unsigned int*)&hh;
                lo[j] = *(unsigned int*)&ll;
            }
            uint32_t off = (uint32_t)(r * TPITCH + ch * 16);
            *(uint4*)(sm + off)      = make_uint4(hi[0], hi[1], hi[2], hi[3]);
            *(uint4*)(sm + TB + off) = make_uint4(lo[0], lo[1], lo[2], lo[3]);
        }
        // B: 2048 chunks / 512 thr = 4 each; bf16 copy (vT rows = d 0..255)
#pragma unroll
        for (int i = 0; i < 4; i++) {
            int idx = tid + i * 512;
            int r  = idx >> 3;
            int ch = idx & 7;
            const long go = (long)r * TT + kt * 64 + ch * 8;
            uint32_t off = (uint32_t)(r * TPITCH + ch * 16);
            *(uint4*)(sm + 2 * TB + off)          = *(const uint4*)(Bh + go);
            *(uint4*)(sm + 2 * TB + PV_BTB + off) = *(const uint4*)(Bl + go);
        }
        __syncthreads();

#pragma unroll
        for (int k16 = 0; k16 < 4; k16++) {
            const uint32_t kb = (uint32_t)(k16 * 32);
            uint32_t ah[2][4], al[2][4];
#pragma unroll
            for (int m = 0; m < 2; m++) {
                uint32_t aa = smb + a_row + (uint32_t)(m * 16 * TPITCH) + kb;
                LDMX4(ah[m][0], ah[m][1], ah[m][2], ah[m][3], aa);
                LDMX4(al[m][0], al[m][1], al[m][2], al[m][3], aa + TB);
            }
#pragma unroll
            for (int np = 0; np < 4; np++) {
                uint32_t ba = smb + 2 * TB + b_row + (uint32_t)(np * 16 * TPITCH) + kb;
                uint32_t bh[4], bl[4];
                LDMX4(bh[0], bh[1], bh[2], bh[3], ba);
                LDMX4(bl[0], bl[1], bl[2], bl[3], ba + PV_BTB);
#pragma unroll
                for (int m = 0; m < 2; m++) {
                    MMA16816(acc[m][np*2],   ah[m], bh[0], bh[1]);
                    MMA16816(acc[m][np*2],   al[m], bh[0], bh[1]);
                    MMA16816(acc[m][np*2],   ah[m], bl[0], bl[1]);
                    MMA16816(acc[m][np*2+1], ah[m], bh[2], bh[3]);
                    MMA16816(acc[m][np*2+1], al[m], bh[2], bh[3]);
                    MMA16816(acc[m][np*2+1], ah[m], bl[2], bl[3]);
                }
            }
        }
    }

#pragma unroll
    for (int m = 0; m < 2; m++) {
        const long r0 = row0 + m0w + m * 16 + (lane >> 2);
#pragma unroll
        for (int nb = 0; nb < 8; nb++) {
            const int cc = n0w + nb * 8 + (lane & 3) * 2;
            *(float2*)(C + r0 * D_EMB + cc)       = make_float2(acc[m][nb][0], acc[m][nb][1]);
            *(float2*)(C + (r0 + 8) * D_EMB + cc) = make_float2(acc[m][nb][2], acc[m][nb][3]);
        }
    }
}

// ---------------- row stats: (max, 1/sumexp) per S row ----------------
__device__ __forceinline__ float warp_red_max(float v) {
#pragma unroll
    for (int o = 16; o; o >>= 1) v = fmaxf(v, __shfl_xor_sync(0xffffffffu, v, o));
    return v;
}
__device__ __forceinline__ float warp_red_sum(float v) {
#pragma unroll
    for (int o = 16; o; o >>= 1) v += __shfl_xor_sync(0xffffffffu, v, o);
    return v;
}

__global__ __launch_bounds__(256)
void row_stats(const float* __restrict__ S, float2* __restrict__ stat)
{
    const long row = blockIdx.x;
    const float* p = S + row * TT;
    const int tid = threadIdx.x;
    __shared__ float red[8];

    float v[16];
#pragma unroll
    for (int j = 0; j < 16; j++) v[j] = p[tid + j * 256];

    float m = -3.4e38f;
#pragma unroll
    for (int j = 0; j < 16; j++) m = fmaxf(m, v[j]);
    m = warp_red_max(m);
    if ((tid & 31) == 0) red[tid >> 5] = m;
    __syncthreads();
    m = red[0];
#pragma unroll
    for (int i = 1; i < 8; i++) m = fmaxf(m, red[i]);
    __syncthreads();

    float s = 0.f;
#pragma unroll
    for (int j = 0; j < 16; j++) s += __expf(v[j] - m);
    s = warp_red_sum(s);
    if ((tid & 31) == 0) red[tid >> 5] = s;
    __syncthreads();
    if (tid == 0) {
        s = 0.f;
#pragma unroll
        for (int i = 0; i < 8; i++) s += red[i];
        stat[row] = make_float2(m, 1.f / s);
    }
}

// ---------------- elementwise split: fp32 -> bf16 hi/lo ----------------
__global__ __launch_bounds__(256)
void split2(const float* __restrict__ in, __nv_bfloat16* __restrict__ oh,
            __nv_bfloat16* __restrict__ ol)
{
    const long i = (long)blockIdx.x * 256 + threadIdx.x;
    float2 v = ((const float2*)in)[i];
    __nv_bfloat16 h0, l0, h1, l1;
    split1(v.x, h0, l0); split1(v.y, h1, l1);
    ((__nv_bfloat162*)oh)[i] = __nv_bfloat162(h0, h1);
    ((__nv_bfloat162*)ol)[i] = __nv_bfloat162(l0, l1);
}

// ---------------- tiled transpose + split ----------------
__global__ __launch_bounds__(256)
void transpose_split(const float* __restrict__ in,
                     __nv_bfloat16* __restrict__ oh, __nv_bfloat16* __restrict__ ol,
                     int rows, int cols, long sIn, long sOut)
{
    __shared__ float t[32][33];
    in += (long)blockIdx.z * sIn;
    oh += (long)blockIdx.z * sOut;  ol += (long)blockIdx.z * sOut;
    const int c0 = blockIdx.x * 32, r0 = blockIdx.y * 32;
    const int tx = threadIdx.x & 31, ty = threadIdx.x >> 5;
#pragma unroll
    for (int i = 0; i < 32; i += 8)
        t[ty + i][tx] = in[(long)(r0 + ty + i) * cols + c0 + tx];
    __syncthreads();
#pragma unroll
    for (int i = 0; i < 32; i += 8) {
        __nv_bfloat16 h, l;
        split1(t[tx][ty + i], h, l);
        const long o = (long)(c0 + ty + i) * rows + r0 + tx;
        oh[o] = h;  ol[o] = l;
    }
}

// ---------------- warp-per-row LayerNorm (D=256) ----------------
__device__ __forceinline__ void ln_row(const float* __restrict__ in,
                                       float v[8], int lane,
                                       const float* __restrict__ w,
                                       const float* __restrict__ b)
{
#pragma unroll
    for (int j = 0; j < 8; j++) v[j] = in[lane + j * 32];
    float s = 0.f;
#pragma unroll
    for (int j = 0; j < 8; j++) s += v[j];
    const float mean = warp_red_sum(s) * (1.f / 256.f);
    float q = 0.f;
#pragma unroll
    for (int j = 0; j < 8; j++) { float d = v[j] - mean; q += d * d; }
    const float rstd = rsqrtf(warp_red_sum(q) * (1.f / 256.f) + EPSLN);
#pragma unroll
    for (int j = 0; j < 8; j++) {
        const int e = lane + j * 32;
        v[j] = (v[j] - mean) * rstd * w[e] + b[e];
    }
}

__global__ __launch_bounds__(256)
void ln_qk(const float* __restrict__ wq, const float* __restrict__ bq,
           const float* __restrict__ wk, const float* __restrict__ bk,
           __nv_bfloat16* __restrict__ qh, __nv_bfloat16* __restrict__ ql,
           __nv_bfloat16* __restrict__ kh, __nv_bfloat16* __restrict__ kl)
{
    const int tensor = blockIdx.y;
    const float* base = g_qkv + (long)tensor * BT * D_EMB;
    const float* w = tensor ? wk : wq;
    const float* b = tensor ? bk : bq;
    __nv_bfloat16* oh = tensor ? kh : qh;
    __nv_bfloat16* ol = tensor ? kl : ql;
    const long row = (long)blockIdx.x * 8 + (threadIdx.x >> 5);
    const int lane = threadIdx.x & 31;
    float v[8];
    ln_row(base + row * D_EMB, v, lane, w, b);
#pragma unroll
    for (int j = 0; j < 8; j++) {
        __nv_bfloat16 h, l;
        split1(v[j], h, l);
        oh[row * D_EMB + lane + j * 32] = h;
        ol[row * D_EMB + lane + j * 32] = l;
    }
}

__global__ __launch_bounds__(256)
void attn_ln_res(const float* __restrict__ x,
                 const float* __restrict__ w, const float* __restrict__ b,
                 __nv_bfloat16* __restrict__ oh, __nv_bfloat16* __restrict__ ol)
{
    const long row = (long)blockIdx.x * 8 + (threadIdx.x >> 5);
    const int lane = threadIdx.x & 31;
    float v[8];
    ln_row(g_y + row * D_EMB, v, lane, w, b);
#pragma unroll
    for (int j = 0; j < 8; j++) {
        const long e = row * D_EMB + lane + j * 32;
        const float r = 0.7f * (x[e] + v[j]);
        g_x1[e] = r;
        __nv_bfloat16 h, l;
        split1(r, h, l);
        oh[e] = h;  ol[e] = l;
    }
}

__global__ __launch_bounds__(256)
void ff_ln_res(float* __restrict__ out,
               const float* __restrict__ w, const float* __restrict__ b)
{
    const long row = (long)blockIdx.x * 8 + (threadIdx.x >> 5);
    const int lane = threadIdx.x & 31;
    float v[8];
    ln_row(g_y2 + row * D_EMB, v, lane, w, b);
#pragma unroll
    for (int j = 0; j < 8; j++) {
        const long e = row * D_EMB + lane + j * 32;
        out[e] = 0.7f * (g_x1[e] + v[j]);
    }
}

// ---------------- launch ----------------
extern "C" void kernel_launch(void* const* d_in, const int* in_sizes, int n_in,
                              void* d_out, int out_size)
{
    const float* x      = (const float*)d_in[0];
    const float* qkvw   = (const float*)d_in[1];
    const float* ln_q_w = (const float*)d_in[2];
    const float* ln_q_b = (const float*)d_in[3];
    const float* ln_k_w = (const float*)d_in[4];
    const float* ln_k_b = (const float*)d_in[5];
    const float* ln_a_w = (const float*)d_in[6];
    const float* ln_a_b = (const float*)d_in[7];
    const float* w1     = (const float*)d_in[8];
    const float* w2     = (const float*)d_in[9];
    const float* ln_f_w = (const float*)d_in[10];
    const float* ln_f_b = (const float*)d_in[11];
    float* out = (float*)d_out;

    float *p_qkv, *p_scores, *p_y, *p_y2;
    float2* p_stat;
    __nv_bfloat16 *xs_h, *xs_l, *qts_h, *qts_l, *q_h, *q_l, *k_h, *k_l;
    __nv_bfloat16 *vts_h, *vts_l, *x1s_h, *x1s_l, *hs_h, *hs_l;
    __nv_bfloat16 *w1s_h, *w1s_l, *w2s_h, *w2s_l;
    cudaGetSymbolAddress((void**)&p_qkv,    g_qkv);
    cudaGetSymbolAddress((void**)&p_scores, g_scores);
    cudaGetSymbolAddress((void**)&p_stat,   g_stat);
    cudaGetSymbolAddress((void**)&p_y,      g_y);
    cudaGetSymbolAddress((void**)&p_y2,     g_y2);
    cudaGetSymbolAddress((void**)&xs_h,  g_xs_h);   cudaGetSymbolAddress((void**)&xs_l,  g_xs_l);
    cudaGetSymbolAddress((void**)&qts_h, g_qts_h);  cudaGetSymbolAddress((void**)&qts_l, g_qts_l);
    cudaGetSymbolAddress((void**)&q_h,   g_q_h);    cudaGetSymbolAddress((void**)&q_l,   g_q_l);
    cudaGetSymbolAddress((void**)&k_h,   g_k_h);    cudaGetSymbolAddress((void**)&k_l,   g_k_l);
    cudaGetSymbolAddress((void**)&vts_h, g_vts_h);  cudaGetSymbolAddress((void**)&vts_l, g_vts_l);
    cudaGetSymbolAddress((void**)&x1s_h, g_x1s_h);  cudaGetSymbolAddress((void**)&x1s_l, g_x1s_l);
    cudaGetSymbolAddress((void**)&hs_h,  g_hs_h);   cudaGetSymbolAddress((void**)&hs_l,  g_hs_l);
    cudaGetSymbolAddress((void**)&w1s_h, g_w1s_h);  cudaGetSymbolAddress((void**)&w1s_l, g_w1s_l);
    cudaGetSymbolAddress((void**)&w2s_h, g_w2s_h);  cudaGetSymbolAddress((void**)&w2s_l, g_w2s_l);

    cudaFuncSetAttribute(gemm_tc, cudaFuncAttributeMaxDynamicSharedMemorySize, GEMM_SMEM);
    cudaFuncSetAttribute(gemm_pv, cudaFuncAttributeMaxDynamicSharedMemorySize, PV_SMEM);

    // 0) input splits
    split2<<<BT * D_EMB / 512, 256>>>(x, xs_h, xs_l);
    split2<<<2 * D_EMB * D_EMB / 512, 256>>>(w1, w1s_h, w1s_l);
    split2<<<2 * D_EMB * D_EMB / 512, 256>>>(w2, w2s_h, w2s_l);
    transpose_split<<<dim3(8, 8, 3), 256>>>(qkvw, qts_h, qts_l, 256, 256,
                                            (long)D_EMB * D_EMB, (long)D_EMB * D_EMB);

    // 1) q,k,v = x @ qkvT^T (fp32 out)
    gemm_tc<<<dim3(2, 128, 3), 256, GEMM_SMEM>>>(
        xs_h, xs_l, qts_h, qts_l, p_qkv, nullptr, nullptr,
        D_EMB, D_EMB, 0L, (long)D_EMB * D_EMB, (long)BT * D_EMB, 1.f, 0);

    // 2) vT split per batch
    transpose_split<<<dim3(8, 128, BB), 256>>>(p_qkv + 2L * BT * D_EMB, vts_h, vts_l,
                                               TT, D_EMB, (long)TT * D_EMB, (long)TT * D_EMB);

    // 3) LN(q), LN(k) -> splits
    ln_qk<<<dim3(BT / 8, 2), 256>>>(ln_q_w, ln_q_b, ln_k_w, ln_k_b, q_h, q_l, k_h, k_l);

    // 4) S = q @ k^T / 16
    gemm_tc<<<dim3(32, 32, BB), 256, GEMM_SMEM>>>(
        q_h, q_l, k_h, k_l, p_scores, nullptr, nullptr,
        D_EMB, TT, (long)TT * D_EMB, (long)TT * D_EMB, (long)TT * TT, 1.f / 16.f, 0);

    // 5) row stats (max, 1/sumexp)
    row_stats<<<BB * TT, 256>>>(p_scores, p_stat);

    // 6) y = softmax(S) @ V  (S read once, exp fused into load)
    gemm_pv<<<dim3(1, 32, BB), 512, PV_SMEM>>>(p_scores, p_stat, vts_h, vts_l, p_y);

    // 7) x1 = 0.7*(x + LN(y)) -> fp32 + split
    attn_ln_res<<<BT / 8, 256>>>(x, ln_a_w, ln_a_b, x1s_h, x1s_l);

    // 8) h = leaky(x1 @ w1^T) -> bf16 split
    gemm_tc<<<dim3(4, 128, 1), 256, GEMM_SMEM>>>(
        x1s_h, x1s_l, w1s_h, w1s_l, nullptr, hs_h, hs_l,
        D_EMB, 2 * D_EMB, 0L, 0L, 0L, 1.f, 2);

    // 9) y2 = leaky(h @ w2^T) (fp32 out)
    gemm_tc<<<dim3(2, 128, 1), 256, GEMM_SMEM>>>(
        hs_h, hs_l, w2s_h, w2s_l, p_y2, nullptr, nullptr,
        2 * D_EMB, D_EMB, 0L, 0L, 0L, 1.f, 1);

    // 10) out = 0.7 * (x1 + LN(y2))
    ff_ln_res<<<BT / 8, 256>>>(out, ln_f_w, ln_f_b);
}

// round 12
// speedup vs baseline: 1.0645x; 1.0295x over previous
#include <cuda_runtime.h>
#include <cuda_bf16.h>
#include <math.h>
#include <stdint.h>

#define D_EMB 256
#define TT    4096
#define BB    4
#define BT    (BB*TT)          // 16384 rows
#define EPSLN 1e-5f

// ---------------- scratch (static device globals: allocation-free) ----------------
__device__ float  g_qkv[3L * BT * D_EMB];            // q,k,v fp32
__device__ float  g_scores[(long)BB * TT * TT];      // scaled scores S
__device__ float2 g_stat[(long)BB * TT];             // (rowmax, 1/sumexp)
__device__ float  g_y [BT * D_EMB];                  // attn out
__device__ float  g_x1[BT * D_EMB];                  // post-attn residual
__device__ float  g_y2[BT * D_EMB];                  // ffn out

// bf16 hi/lo split operands
__device__ __nv_bfloat16 g_xs_h [BT * D_EMB],        g_xs_l [BT * D_EMB];
__device__ __nv_bfloat16 g_qts_h[3 * D_EMB * D_EMB], g_qts_l[3 * D_EMB * D_EMB];
__device__ __nv_bfloat16 g_q_h  [BT * D_EMB],        g_q_l  [BT * D_EMB];
__device__ __nv_bfloat16 g_k_h  [BT * D_EMB],        g_k_l  [BT * D_EMB];
__device__ __nv_bfloat16 g_vts_h[BT * D_EMB],        g_vts_l[BT * D_EMB];
__device__ __nv_bfloat16 g_x1s_h[BT * D_EMB],        g_x1s_l[BT * D_EMB];
__device__ __nv_bfloat16 g_hs_h [BT * 2 * D_EMB],    g_hs_l [BT * 2 * D_EMB];
__device__ __nv_bfloat16 g_w1s_h[2 * D_EMB * D_EMB], g_w1s_l[2 * D_EMB * D_EMB];
__device__ __nv_bfloat16 g_w2s_h[2 * D_EMB * D_EMB], g_w2s_l[2 * D_EMB * D_EMB];

// ================= helpers (baseline PTX, no 'a' features) =================
__device__ __forceinline__ uint32_t smem_to_u32(const void* p) {
    uint32_t a;
    asm("{ .reg .u64 t; cvta.to.shared.u64 t, %1; cvt.u32.u64 %0, t; }" : "=r"(a) : "l"(p));
    return a;
}
#define LDMX4(r0, r1, r2, r3, addr) \
    asm volatile("ldmatrix.sync.aligned.m8n8.x4.shared.b16 {%0,%1,%2,%3}, [%4];" \
        : "=r"(r0), "=r"(r1), "=r"(r2), "=r"(r3) : "r"(addr))
#define MMA16816(c, a, b0v, b1v) \
    asm volatile("mma.sync.aligned.m16n8k16.row.col.f32.bf16.bf16.f32 " \
        "{%0,%1,%2,%3}, {%4,%5,%6,%7}, {%8,%9}, {%0,%1,%2,%3};" \
        : "+f"((c)[0]), "+f"((c)[1]), "+f"((c)[2]), "+f"((c)[3]) \
        : "r"((a)[0]), "r"((a)[1]), "r"((a)[2]), "r"((a)[3]), "r"(b0v), "r"(b1v))

__device__ __forceinline__ void split1(float v, __nv_bfloat16& h, __nv_bfloat16& l) {
    h = __float2bfloat16(v);
    l = __float2bfloat16(v - __bfloat162float(h));
}

// smem tile: 128 rows x 64 bf16, row pitch 144 B (R8-proven ldmatrix layout)
#define TPITCH 144
#define TB     (128 * TPITCH)        // 18432
#define GEMM_SMEM (4 * TB)           // AH, AL, BH, BL: 73728

// copy one 128x64 bf16 tile (pre-split source) into smem; 256 threads
__device__ __forceinline__ void load_bf16_tile(const __nv_bfloat16* __restrict__ g, int ld,
                                               char* sm, int off, int tid)
{
#pragma unroll
    for (int i = 0; i < 4; i++) {
        int idx = tid + i * 256;
        int r  = idx >> 3;
        int ch = idx & 7;
        *(uint4*)(sm + off + r * TPITCH + ch * 16) =
            *(const uint4*)(g + (long)r * ld + ch * 8);
    }
}

// ---------------- generic 256-thread GEMM (R8 engine, bf16-copy loads) ----------------
// C[M,N] = epi(alpha * (Ah+Al)[M,K] @ (Bh+Bl)[N,K]^T), 3-product fp32 emulation
// epi: 0 none (fp32 C), 1 leaky (fp32 C), 2 leaky + bf16 split out (Ch, Cl)
__global__ __launch_bounds__(256, 2)
void gemm_tc(const __nv_bfloat16* __restrict__ Ah, const __nv_bfloat16* __restrict__ Al,
             const __nv_bfloat16* __restrict__ Bh, const __nv_bfloat16* __restrict__ Bl,
             float* __restrict__ C, __nv_bfloat16* __restrict__ Ch, __nv_bfloat16* __restrict__ Cl,
             int K, int N, long sA, long sB, long sC, float alpha, int epi)
{
    extern __shared__ char sm[];
    const uint32_t smb = smem_to_u32(sm);
    const int tid  = threadIdx.x;
    const int wid  = tid >> 5;
    const int lane = tid & 31;

    Ah += blockIdx.z * sA;  Al += blockIdx.z * sA;
    Bh += blockIdx.z * sB;  Bl += blockIdx.z * sB;
    const int row0 = blockIdx.y * 128;
    const int col0 = blockIdx.x * 128;

    const int m0w = (wid & 3) * 32;
    const int n0w = (wid >> 2) * 64;

    float acc[2][8][4];
#pragma unroll
    for (int m = 0; m < 2; m++)
#pragma unroll
        for (int n = 0; n < 8; n++)
#pragma unroll
            for (int j = 0; j < 4; j++) acc[m][n][j] = 0.f;

    const uint32_t a_row = (uint32_t)((m0w + (lane & 15)) * TPITCH) + ((lane & 16) ? 16u : 0u);
    const uint32_t b_row = (uint32_t)((n0w + (lane & 7) + ((lane & 16) >> 1)) * TPITCH)
                         + ((lane & 8) ? 16u : 0u);

    const int KT = K >> 6;
    for (int kt = 0; kt < KT; kt++) {
        if (kt) __syncthreads();
        const long ko = (long)kt * 64;
        load_bf16_tile(Ah + (long)row0 * K + ko, K, sm, 0,      tid);
        load_bf16_tile(Al + (long)row0 * K + ko, K, sm, TB,     tid);
        load_bf16_tile(Bh + (long)col0 * K + ko, K, sm, 2 * TB, tid);
        load_bf16_tile(Bl + (long)col0 * K + ko, K, sm, 3 * TB, tid);
        __syncthreads();

#pragma unroll
        for (int k16 = 0; k16 < 4; k16++) {
            const uint32_t kb = (uint32_t)(k16 * 32);
            uint32_t ah[2][4], al[2][4];
#pragma unroll
            for (int m = 0; m < 2; m++) {
                uint32_t aa = smb + a_row + (uint32_t)(m * 16 * TPITCH) + kb;
                LDMX4(ah[m][0], ah[m][1], ah[m][2], ah[m][3], aa);
                LDMX4(al[m][0], al[m][1], al[m][2], al[m][3], aa + TB);
            }
#pragma unroll
            for (int np = 0; np < 4; np++) {
                uint32_t ba = smb + 2 * TB + b_row + (uint32_t)(np * 16 * TPITCH) + kb;
                uint32_t bh[4], bl[4];
                LDMX4(bh[0], bh[1], bh[2], bh[3], ba);
                LDMX4(bl[0], bl[1], bl[2], bl[3], ba + TB);
#pragma unroll
                for (int m = 0; m < 2; m++) {
                    MMA16816(acc[m][np*2],   ah[m], bh[0], bh[1]);
                    MMA16816(acc[m][np*2],   al[m], bh[0], bh[1]);
                    MMA16816(acc[m][np*2],   ah[m], bl[0], bl[1]);
                    MMA16816(acc[m][np*2+1], ah[m], bh[2], bh[3]);
                    MMA16816(acc[m][np*2+1], al[m], bh[2], bh[3]);
                    MMA16816(acc[m][np*2+1], ah[m], bl[2], bl[3]);
                }
            }
        }
    }

    C  += blockIdx.z * sC;
    Ch += blockIdx.z * sC;  Cl += blockIdx.z * sC;
#pragma unroll
    for (int m = 0; m < 2; m++) {
        const long r0 = row0 + m0w + m * 16 + (lane >> 2);
#pragma unroll
        for (int nb = 0; nb < 8; nb++) {
            const int cc = col0 + n0w + nb * 8 + (lane & 3) * 2;
            float v[4];
            v[0] = alpha * acc[m][nb][0];  v[1] = alpha * acc[m][nb][1];
            v[2] = alpha * acc[m][nb][2];  v[3] = alpha * acc[m][nb][3];
            if (epi >= 1) {
#pragma unroll
                for (int j = 0; j < 4; j++) v[j] = v[j] > 0.f ? v[j] : 0.2f * v[j];
            }
            if (epi == 2) {
                __nv_bfloat16 h0, l0, h1, l1;
                split1(v[0], h0, l0); split1(v[1], h1, l1);
                *(__nv_bfloat162*)(Ch + r0 * N + cc) = __nv_bfloat162(h0, h1);
                *(__nv_bfloat162*)(Cl + r0 * N + cc) = __nv_bfloat162(l0, l1);
                split1(v[2], h0, l0); split1(v[3], h1, l1);
                *(__nv_bfloat162*)(Ch + (r0 + 8) * N + cc) = __nv_bfloat162(h0, h1);
                *(__nv_bfloat162*)(Cl + (r0 + 8) * N + cc) = __nv_bfloat162(l0, l1);
            } else {
                *(float2*)(C + r0 * N + cc)       = make_float2(v[0], v[1]);
                *(float2*)(C + (r0 + 8) * N + cc) = make_float2(v[2], v[3]);
            }
        }
    }
}

// ---------------- PV GEMM: y = softmax(S) @ V ----------------
// R8-proven shape: 256 threads, 128x128 tile, occ 2, grid (2, 32, BB).
// A-tile load reads S fp32 once per CTA and applies exp(s-m)*inv + hi/lo split.
__global__ __launch_bounds__(256, 2)
void gemm_pv(const float* __restrict__ S, const float2* __restrict__ stat,
             const __nv_bfloat16* __restrict__ Bh, const __nv_bfloat16* __restrict__ Bl,
             float* __restrict__ C)
{
    extern __shared__ char sm[];
    const uint32_t smb = smem_to_u32(sm);
    const int tid  = threadIdx.x;
    const int wid  = tid >> 5;
    const int lane = tid & 31;

    S    += (long)blockIdx.z * TT * TT;
    stat += (long)blockIdx.z * TT;
    Bh   += (long)blockIdx.z * D_EMB * TT;
    Bl   += (long)blockIdx.z * D_EMB * TT;
    C    += (long)blockIdx.z * TT * D_EMB;
    const int row0 = blockIdx.y * 128;
    const int col0 = blockIdx.x * 128;

    const int m0w = (wid & 3) * 32;
    const int n0w = (wid >> 2) * 64;

    float acc[2][8][4];
#pragma unroll
    for (int m = 0; m < 2; m++)
#pragma unroll
        for (int n = 0; n < 8; n++)
#pragma unroll
            for (int j = 0; j < 4; j++) acc[m][n][j] = 0.f;

    const uint32_t a_row = (uint32_t)((m0w + (lane & 15)) * TPITCH) + ((lane & 16) ? 16u : 0u);
    const uint32_t b_row = (uint32_t)((n0w + (lane & 7) + ((lane & 16) >> 1)) * TPITCH)
                         + ((lane & 8) ? 16u : 0u);

    // per-thread A-load row/chunk (4 iters of 256)
    for (int kt = 0; kt < TT / 64; kt++) {
        if (kt) __syncthreads();
        // A: S fp32 -> p = exp(s-m)*inv -> bf16 hi/lo split (1024 chunks / 256 thr)
#pragma unroll
        for (int i = 0; i < 4; i++) {
            int idx = tid + i * 256;
            int r  = idx >> 3;
            int ch = idx & 7;
            const float* p = S + (long)(row0 + r) * TT + kt * 64 + ch * 8;
            float2 st = stat[row0 + r];       // (m, inv)
            float4 f0 = *(const float4*)p;
            float4 f1 = *(const float4*)(p + 4);
            float f[8] = {f0.x, f0.y, f0.z, f0.w, f1.x, f1.y, f1.z, f1.w};
            unsigned int hi[4], lo[4];
#pragma unroll
            for (int j = 0; j < 4; j++) {
                float p0 = __expf(f[2*j]   - st.x) * st.y;
                float p1 = __expf(f[2*j+1] - st.x) * st.y;
                __nv_bfloat16 h0, l0, h1, l1;
                split1(p0, h0, l0); split1(p1, h1, l1);
                __nv_bfloat162 hh(h0, h1), ll(l0, l1);
                hi[j] = *(unsigned int*)&hh;
                lo[j] = *(unsigned int*)&ll;
            }
            uint32_t off = (uint32_t)(r * TPITCH + ch * 16);
            *(uint4*)(sm + off)      = make_uint4(hi[0], hi[1], hi[2], hi[3]);
            *(uint4*)(sm + TB + off) = make_uint4(lo[0], lo[1], lo[2], lo[3]);
        }
        // B: vT bf16 copy (rows = d in col0..col0+127)
        load_bf16_tile(Bh + (long)col0 * TT + kt * 64, TT, sm, 2 * TB, tid);
        load_bf16_tile(Bl + (long)col0 * TT + kt * 64, TT, sm, 3 * TB, tid);
        __syncthreads();

#pragma unroll
        for (int k16 = 0; k16 < 4; k16++) {
            const uint32_t kb = (uint32_t)(k16 * 32);
            uint32_t ah[2][4], al[2][4];
#pragma unroll
            for (int m = 0; m < 2; m++) {
                uint32_t aa = smb + a_row + (uint32_t)(m * 16 * TPITCH) + kb;
                LDMX4(ah[m][0], ah[m][1], ah[m][2], ah[m][3], aa);
                LDMX4(al[m][0], al[m][1], al[m][2], al[m][3], aa + TB);
            }
#pragma unroll
            for (int np = 0; np < 4; np++) {
                uint32_t ba = smb + 2 * TB + b_row + (uint32_t)(np * 16 * TPITCH) + kb;
                uint32_t bh[4], bl[4];
                LDMX4(bh[0], bh[1], bh[2], bh[3], ba);
                LDMX4(bl[0], bl[1], bl[2], bl[3], ba + TB);
#pragma unroll
                for (int m = 0; m < 2; m++) {
                    MMA16816(acc[m][np*2],   ah[m], bh[0], bh[1]);
                    MMA16816(acc[m][np*2],   al[m], bh[0], bh[1]);
                    MMA16816(acc[m][np*2],   ah[m], bl[0], bl[1]);
                    MMA16816(acc[m][np*2+1], ah[m], bh[2], bh[3]);
                    MMA16816(acc[m][np*2+1], al[m], bh[2], bh[3]);
                    MMA16816(acc[m][np*2+1], ah[m], bl[2], bl[3]);
                }
            }
        }
    }

#pragma unroll
    for (int m = 0; m < 2; m++) {
        const long r0 = row0 + m0w + m * 16 + (lane >> 2);
#pragma unroll
        for (int nb = 0; nb < 8; nb++) {
            const int cc = col0 + n0w + nb * 8 + (lane & 3) * 2;
            *(float2*)(C + r0 * D_EMB + cc)       = make_float2(acc[m][nb][0], acc[m][nb][1]);
            *(float2*)(C + (r0 + 8) * D_EMB + cc) = make_float2(acc[m][nb][2], acc[m][nb][3]);
        }
    }
}

// ---------------- row stats: (max, 1/sumexp) per S row ----------------
__device__ __forceinline__ float warp_red_max(float v) {
#pragma unroll
    for (int o = 16; o; o >>= 1) v = fmaxf(v, __shfl_xor_sync(0xffffffffu, v, o));
    return v;
}
__device__ __forceinline__ float warp_red_sum(float v) {
#pragma unroll
    for (int o = 16; o; o >>= 1) v += __shfl_xor_sync(0xffffffffu, v, o);
    return v;
}

__global__ __launch_bounds__(256)
void row_stats(const float* __restrict__ S, float2* __restrict__ stat)
{
    const long row = blockIdx.x;
    const float* p = S + row * TT;
    const int tid = threadIdx.x;
    __shared__ float red[8];

    float v[16];
#pragma unroll
    for (int j = 0; j < 16; j++) v[j] = p[tid + j * 256];

    float m = -3.4e38f;
#pragma unroll
    for (int j = 0; j < 16; j++) m = fmaxf(m, v[j]);
    m = warp_red_max(m);
    if ((tid & 31) == 0) red[tid >> 5] = m;
    __syncthreads();
    m = red[0];
#pragma unroll
    for (int i = 1; i < 8; i++) m = fmaxf(m, red[i]);
    __syncthreads();

    float s = 0.f;
#pragma unroll
    for (int j = 0; j < 16; j++) s += __expf(v[j] - m);
    s = warp_red_sum(s);
    if ((tid & 31) == 0) red[tid >> 5] = s;
    __syncthreads();
    if (tid == 0) {
        s = 0.f;
#pragma unroll
        for (int i = 0; i < 8; i++) s += red[i];
        stat[row] = make_float2(m, 1.f / s);
    }
}

// ---------------- elementwise split: fp32 -> bf16 hi/lo ----------------
__global__ __launch_bounds__(256)
void split2(const float* __restrict__ in, __nv_bfloat16* __restrict__ oh,
            __nv_bfloat16* __restrict__ ol)
{
    const long i = (long)blockIdx.x * 256 + threadIdx.x;
    float2 v = ((const float2*)in)[i];
    __nv_bfloat16 h0, l0, h1, l1;
    split1(v.x, h0, l0); split1(v.y, h1, l1);
    ((__nv_bfloat162*)oh)[i] = __nv_bfloat162(h0, h1);
    ((__nv_bfloat162*)ol)[i] = __nv_bfloat162(l0, l1);
}

// ---------------- tiled transpose + split ----------------
__global__ __launch_bounds__(256)
void transpose_split(const float* __restrict__ in,
                     __nv_bfloat16* __restrict__ oh, __nv_bfloat16* __restrict__ ol,
                     int rows, int cols, long sIn, long sOut)
{
    __shared__ float t[32][33];
    in += (long)blockIdx.z * sIn;
    oh += (long)blockIdx.z * sOut;  ol += (long)blockIdx.z * sOut;
    const int c0 = blockIdx.x * 32, r0 = blockIdx.y * 32;
    const int tx = threadIdx.x & 31, ty = threadIdx.x >> 5;
#pragma unroll
    for (int i = 0; i < 32; i += 8)
        t[ty + i][tx] = in[(long)(r0 + ty + i) * cols + c0 + tx];
    __syncthreads();
#pragma unroll
    for (int i = 0; i < 32; i += 8) {
        __nv_bfloat16 h, l;
        split1(t[tx][ty + i], h, l);
        const long o = (long)(c0 + ty + i) * rows + r0 + tx;
        oh[o] = h;  ol[o] = l;
    }
}

// ---------------- warp-per-row LayerNorm (D=256) ----------------
__device__ __forceinline__ void ln_row(const float* __restrict__ in,
                                       float v[8], int lane,
                                       const float* __restrict__ w,
                                       const float* __restrict__ b)
{
#pragma unroll
    for (int j = 0; j < 8; j++) v[j] = in[lane + j * 32];
    float s = 0.f;
#pragma unroll
    for (int j = 0; j < 8; j++) s += v[j];
    const float mean = warp_red_sum(s) * (1.f / 256.f);
    float q = 0.f;
#pragma unroll
    for (int j = 0; j < 8; j++) { float d = v[j] - mean; q += d * d; }
    const float rstd = rsqrtf(warp_red_sum(q) * (1.f / 256.f) + EPSLN);
#pragma unroll
    for (int j = 0; j < 8; j++) {
        const int e = lane + j * 32;
        v[j] = (v[j] - mean) * rstd * w[e] + b[e];
    }
}

__global__ __launch_bounds__(256)
void ln_qk(const float* __restrict__ wq, const float* __restrict__ bq,
           const float* __restrict__ wk, const float* __restrict__ bk,
           __nv_bfloat16* __restrict__ qh, __nv_bfloat16* __restrict__ ql,
           __nv_bfloat16* __restrict__ kh, __nv_bfloat16* __restrict__ kl)
{
    const int tensor = blockIdx.y;
    const float* base = g_qkv + (long)tensor * BT * D_EMB;
    const float* w = tensor ? wk : wq;
    const float* b = tensor ? bk : bq;
    __nv_bfloat16* oh = tensor ? kh : qh;
    __nv_bfloat16* ol = tensor ? kl : ql;
    const long row = (long)blockIdx.x * 8 + (threadIdx.x >> 5);
    const int lane = threadIdx.x & 31;
    float v[8];
    ln_row(base + row * D_EMB, v, lane, w, b);
#pragma unroll
    for (int j = 0; j < 8; j++) {
        __nv_bfloat16 h, l;
        split1(v[j], h, l);
        oh[row * D_EMB + lane + j * 32] = h;
        ol[row * D_EMB + lane + j * 32] = l;
    }
}

__global__ __launch_bounds__(256)
void attn_ln_res(const float* __restrict__ x,
                 const float* __restrict__ w, const float* __restrict__ b,
                 __nv_bfloat16* __restrict__ oh, __nv_bfloat16* __restrict__ ol)
{
    const long row = (long)blockIdx.x * 8 + (threadIdx.x >> 5);
    const int lane = threadIdx.x & 31;
    float v[8];
    ln_row(g_y + row * D_EMB, v, lane, w, b);
#pragma unroll
    for (int j = 0; j < 8; j++) {
        const long e = row * D_EMB + lane + j * 32;
        const float r = 0.7f * (x[e] + v[j]);
        g_x1[e] = r;
        __nv_bfloat16 h, l;
        split1(r, h, l);
        oh[e] = h;  ol[e] = l;
    }
}

__global__ __launch_bounds__(256)
void ff_ln_res(float* __restrict__ out,
               const float* __restrict__ w, const float* __restrict__ b)
{
    const long row = (long)blockIdx.x * 8 + (threadIdx.x >> 5);
    const int lane = threadIdx.x & 31;
    float v[8];
    ln_row(g_y2 + row * D_EMB, v, lane, w, b);
#pragma unroll
    for (int j = 0; j < 8; j++) {
        const long e = row * D_EMB + lane + j * 32;
        out[e] = 0.7f * (g_x1[e] + v[j]);
    }
}

// ---------------- launch ----------------
extern "C" void kernel_launch(void* const* d_in, const int* in_sizes, int n_in,
                              void* d_out, int out_size)
{
    const float* x      = (const float*)d_in[0];
    const float* qkvw   = (const float*)d_in[1];
    const float* ln_q_w = (const float*)d_in[2];
    const float* ln_q_b = (const float*)d_in[3];
    const float* ln_k_w = (const float*)d_in[4];
    const float* ln_k_b = (const float*)d_in[5];
    const float* ln_a_w = (const float*)d_in[6];
    const float* ln_a_b = (const float*)d_in[7];
    const float* w1     = (const float*)d_in[8];
    const float* w2     = (const float*)d_in[9];
    const float* ln_f_w = (const float*)d_in[10];
    const float* ln_f_b = (const float*)d_in[11];
    float* out = (float*)d_out;

    float *p_qkv, *p_scores, *p_y, *p_y2;
    float2* p_stat;
    __nv_bfloat16 *xs_h, *xs_l, *qts_h, *qts_l, *q_h, *q_l, *k_h, *k_l;
    __nv_bfloat16 *vts_h, *vts_l, *x1s_h, *x1s_l, *hs_h, *hs_l;
    __nv_bfloat16 *w1s_h, *w1s_l, *w2s_h, *w2s_l;
    cudaGetSymbolAddress((void**)&p_qkv,    g_qkv);
    cudaGetSymbolAddress((void**)&p_scores, g_scores);
    cudaGetSymbolAddress((void**)&p_stat,   g_stat);
    cudaGetSymbolAddress((void**)&p_y,      g_y);
    cudaGetSymbolAddress((void**)&p_y2,     g_y2);
    cudaGetSymbolAddress((void**)&xs_h,  g_xs_h);   cudaGetSymbolAddress((void**)&xs_l,  g_xs_l);
    cudaGetSymbolAddress((void**)&qts_h, g_qts_h);  cudaGetSymbolAddress((void**)&qts_l, g_qts_l);
    cudaGetSymbolAddress((void**)&q_h,   g_q_h);    cudaGetSymbolAddress((void**)&q_l,   g_q_l);
    cudaGetSymbolAddress((void**)&k_h,   g_k_h);    cudaGetSymbolAddress((void**)&k_l,   g_k_l);
    cudaGetSymbolAddress((void**)&vts_h, g_vts_h);  cudaGetSymbolAddress((void**)&vts_l, g_vts_l);
    cudaGetSymbolAddress((void**)&x1s_h, g_x1s_h);  cudaGetSymbolAddress((void**)&x1s_l, g_x1s_l);
    cudaGetSymbolAddress((void**)&hs_h,  g_hs_h);   cudaGetSymbolAddress((void**)&hs_l,  g_hs_l);
    cudaGetSymbolAddress((void**)&w1s_h, g_w1s_h);  cudaGetSymbolAddress((void**)&w1s_l, g_w1s_l);
    cudaGetSymbolAddress((void**)&w2s_h, g_w2s_h);  cudaGetSymbolAddress((void**)&w2s_l, g_w2s_l);

    cudaFuncSetAttribute(gemm_tc, cudaFuncAttributeMaxDynamicSharedMemorySize, GEMM_SMEM);
    cudaFuncSetAttribute(gemm_pv, cudaFuncAttributeMaxDynamicSharedMemorySize, GEMM_SMEM);

    // 0) input splits
    split2<<<BT * D_EMB / 512, 256>>>(x, xs_h, xs_l);
    split2<<<2 * D_EMB * D_EMB / 512, 256>>>(w1, w1s_h, w1s_l);
    split2<<<2 * D_EMB * D_EMB / 512, 256>>>(w2, w2s_h, w2s_l);
    transpose_split<<<dim3(8, 8, 3), 256>>>(qkvw, qts_h, qts_l, 256, 256,
                                            (long)D_EMB * D_EMB, (long)D_EMB * D_EMB);

    // 1) q,k,v = x @ qkvT^T (fp32 out)
    gemm_tc<<<dim3(2, 128, 3), 256, GEMM_SMEM>>>(
        xs_h, xs_l, qts_h, qts_l, p_qkv, nullptr, nullptr,
        D_EMB, D_EMB, 0L, (long)D_EMB * D_EMB, (long)BT * D_EMB, 1.f, 0);

    // 2) vT split per batch
    transpose_split<<<dim3(8, 128, BB), 256>>>(p_qkv + 2L * BT * D_EMB, vts_h, vts_l,
                                               TT, D_EMB, (long)TT * D_EMB, (long)TT * D_EMB);

    // 3) LN(q), LN(k) -> splits
    ln_qk<<<dim3(BT / 8, 2), 256>>>(ln_q_w, ln_q_b, ln_k_w, ln_k_b, q_h, q_l, k_h, k_l);

    // 4) S = q @ k^T / 16
    gemm_tc<<<dim3(32, 32, BB), 256, GEMM_SMEM>>>(
        q_h, q_l, k_h, k_l, p_scores, nullptr, nullptr,
        D_EMB, TT, (long)TT * D_EMB, (long)TT * D_EMB, (long)TT * TT, 1.f / 16.f, 0);

    // 5) row stats (max, 1/sumexp)
    row_stats<<<BB * TT, 256>>>(p_scores, p_stat);

    // 6) y = softmax(S) @ V  (exp fused into A-tile load; R8-proven shape)
    gemm_pv<<<dim3(2, 32, BB), 256, GEMM_SMEM>>>(p_scores, p_stat, vts_h, vts_l, p_y);

    // 7) x1 = 0.7*(x + LN(y)) -> fp32 + split
    attn_ln_res<<<BT / 8, 256>>>(x, ln_a_w, ln_a_b, x1s_h, x1s_l);

    // 8) h = leaky(x1 @ w1^T) -> bf16 split
    gemm_tc<<<dim3(4, 128, 1), 256, GEMM_SMEM>>>(
        x1s_h, x1s_l, w1s_h, w1s_l, nullptr, hs_h, hs_l,
        D_EMB, 2 * D_EMB, 0L, 0L, 0L, 1.f, 2);

    // 9) y2 = leaky(h @ w2^T) (fp32 out)
    gemm_tc<<<dim3(2, 128, 1), 256, GEMM_SMEM>>>(
        hs_h, hs_l, w2s_h, w2s_l, p_y2, nullptr, nullptr,
        2 * D_EMB, D_EMB, 0L, 0L, 0L, 1.f, 1);

    // 10) out = 0.7 * (x1 + LN(y2))
    ff_ln_res<<<BT / 8, 256>>>(out, ln_f_w, ln_f_b);
}

// round 15
// speedup vs baseline: 1.4132x; 1.3276x over previous
#include <cuda_runtime.h>
#include <cuda_fp16.h>
#include <math.h>
#include <stdint.h>

#define D_EMB 256
#define TT    4096
#define BB    4
#define BT    (BB*TT)          // 16384 rows
#define EPSLN 1e-5f

// ---------------- scratch (static device globals: allocation-free) ----------------
__device__ float  g_qkv[3L * BT * D_EMB];            // q,k,v fp32
__device__ float  g_scores[(long)BB * TT * TT];      // scaled scores S
__device__ float2 g_stat[(long)BB * TT];             // (rowmax, 1/sumexp)
__device__ float  g_y [BT * D_EMB];                  // attn out
__device__ float  g_x1[BT * D_EMB];                  // post-attn residual
__device__ float  g_y2[BT * D_EMB];                  // ffn out

// fp16 hi/lo split operands (lo used only on A-side of each GEMM)
__device__ __half g_xs_h [BT * D_EMB],        g_xs_l [BT * D_EMB];
__device__ __half g_qts_h[3 * D_EMB * D_EMB], g_qts_l[3 * D_EMB * D_EMB];
__device__ __half g_q_h  [BT * D_EMB],        g_q_l  [BT * D_EMB];
__device__ __half g_k_h  [BT * D_EMB],        g_k_l  [BT * D_EMB];
__device__ __half g_vts_h[BT * D_EMB],        g_vts_l[BT * D_EMB];
__device__ __half g_x1s_h[BT * D_EMB],        g_x1s_l[BT * D_EMB];
__device__ __half g_hs_h [BT * 2 * D_EMB],    g_hs_l [BT * 2 * D_EMB];
__device__ __half g_w1s_h[2 * D_EMB * D_EMB], g_w1s_l[2 * D_EMB * D_EMB];
__device__ __half g_w2s_h[2 * D_EMB * D_EMB], g_w2s_l[2 * D_EMB * D_EMB];

// ================= helpers (baseline PTX, no 'a' features) =================
__device__ __forceinline__ uint32_t smem_to_u32(const void* p) {
    uint32_t a;
    asm("{ .reg .u64 t; cvta.to.shared.u64 t, %1; cvt.u32.u64 %0, t; }" : "=r"(a) : "l"(p));
    return a;
}
#define LDMX4(r0, r1, r2, r3, addr) \
    asm volatile("ldmatrix.sync.aligned.m8n8.x4.shared.b16 {%0,%1,%2,%3}, [%4];" \
        : "=r"(r0), "=r"(r1), "=r"(r2), "=r"(r3) : "r"(addr))
#define MMA16816(c, a, b0v, b1v) \
    asm volatile("mma.sync.aligned.m16n8k16.row.col.f32.f16.f16.f32 " \
        "{%0,%1,%2,%3}, {%4,%5,%6,%7}, {%8,%9}, {%0,%1,%2,%3};" \
        : "+f"((c)[0]), "+f"((c)[1]), "+f"((c)[2]), "+f"((c)[3]) \
        : "r"((a)[0]), "r"((a)[1]), "r"((a)[2]), "r"((a)[3]), "r"(b0v), "r"(b1v))

// exact fp16 split: v == (float)h + (float)l to ~22 bits
__device__ __forceinline__ void split1(float v, __half& h, __half& l) {
    h = __float2half_rn(v);
    l = __float2half_rn(v - __half2float(h));
}

// smem tile: 128 rows x 64 fp16, row pitch 144 B (proven ldmatrix layout)
#define TPITCH 144
#define TB     (128 * TPITCH)        // 18432
#define GEMM_SMEM (3 * TB)           // AH, AL, BH: 55296

// copy one 128x64 fp16 tile (pre-split source) into smem; 256 threads
__device__ __forceinline__ void load_f16_tile(const __half* __restrict__ g, int ld,
                                              char* sm, int off, int tid)
{
#pragma unroll
    for (int i = 0; i < 4; i++) {
        int idx = tid + i * 256;
        int r  = idx >> 3;
        int ch = idx & 7;
        *(uint4*)(sm + off + r * TPITCH + ch * 16) =
            *(const uint4*)(g + (long)r * ld + ch * 8);
    }
}

// ---------------- 256-thread GEMM: 2-product fp16 emulation ----------------
// C[M,N] = epi(alpha * (Ah+Al)[M,K] @ Bh[N,K]^T)
// epi: 0 none (fp32 C), 1 leaky (fp32 C), 2 leaky + fp16 split out (Ch, Cl)
__global__ __launch_bounds__(256, 2)
void gemm_tc(const __half* __restrict__ Ah, const __half* __restrict__ Al,
             const __half* __restrict__ Bh,
             float* __restrict__ C, __half* __restrict__ Ch, __half* __restrict__ Cl,
             int K, int N, long sA, long sB, long sC, float alpha, int epi)
{
    extern __shared__ char sm[];
    const uint32_t smb = smem_to_u32(sm);
    const int tid  = threadIdx.x;
    const int wid  = tid >> 5;
    const int lane = tid & 31;

    Ah += blockIdx.z * sA;  Al += blockIdx.z * sA;
    Bh += blockIdx.z * sB;
    const int row0 = blockIdx.y * 128;
    const int col0 = blockIdx.x * 128;

    const int m0w = (wid & 3) * 32;
    const int n0w = (wid >> 2) * 64;

    float acc[2][8][4];
#pragma unroll
    for (int m = 0; m < 2; m++)
#pragma unroll
        for (int n = 0; n < 8; n++)
#pragma unroll
            for (int j = 0; j < 4; j++) acc[m][n][j] = 0.f;

    const uint32_t a_row = (uint32_t)((m0w + (lane & 15)) * TPITCH) + ((lane & 16) ? 16u : 0u);
    const uint32_t b_row = (uint32_t)((n0w + (lane & 7) + ((lane & 16) >> 1)) * TPITCH)
                         + ((lane & 8) ? 16u : 0u);

    const int KT = K >> 6;
    for (int kt = 0; kt < KT; kt++) {
        if (kt) __syncthreads();
        const long ko = (long)kt * 64;
        load_f16_tile(Ah + (long)row0 * K + ko, K, sm, 0,      tid);
        load_f16_tile(Al + (long)row0 * K + ko, K, sm, TB,     tid);
        load_f16_tile(Bh + (long)col0 * K + ko, K, sm, 2 * TB, tid);
        __syncthreads();

#pragma unroll
        for (int k16 = 0; k16 < 4; k16++) {
            const uint32_t kb = (uint32_t)(k16 * 32);
            uint32_t ah[2][4], al[2][4];
#pragma unroll
            for (int m = 0; m < 2; m++) {
                uint32_t aa = smb + a_row + (uint32_t)(m * 16 * TPITCH) + kb;
                LDMX4(ah[m][0], ah[m][1], ah[m][2], ah[m][3], aa);
                LDMX4(al[m][0], al[m][1], al[m][2], al[m][3], aa + TB);
            }
#pragma unroll
            for (int np = 0; np < 4; np++) {
                uint32_t ba = smb + 2 * TB + b_row + (uint32_t)(np * 16 * TPITCH) + kb;
                uint32_t bh[4];
                LDMX4(bh[0], bh[1], bh[2], bh[3], ba);
#pragma unroll
                for (int m = 0; m < 2; m++) {
                    MMA16816(acc[m][np*2],   ah[m], bh[0], bh[1]);
                    MMA16816(acc[m][np*2],   al[m], bh[0], bh[1]);
                    MMA16816(acc[m][np*2+1], ah[m], bh[2], bh[3]);
                    MMA16816(acc[m][np*2+1], al[m], bh[2], bh[3]);
                }
            }
        }
    }

    C  += blockIdx.z * sC;
    Ch += blockIdx.z * sC;  Cl += blockIdx.z * sC;
#pragma unroll
    for (int m = 0; m < 2; m++) {
        const long r0 = row0 + m0w + m * 16 + (lane >> 2);
#pragma unroll
        for (int nb = 0; nb < 8; nb++) {
            const int cc = col0 + n0w + nb * 8 + (lane & 3) * 2;
            float v[4];
            v[0] = alpha * acc[m][nb][0];  v[1] = alpha * acc[m][nb][1];
            v[2] = alpha * acc[m][nb][2];  v[3] = alpha * acc[m][nb][3];
            if (epi >= 1) {
#pragma unroll
                for (int j = 0; j < 4; j++) v[j] = v[j] > 0.f ? v[j] : 0.2f * v[j];
            }
            if (epi == 2) {
                __half h0, l0, h1, l1;
                split1(v[0], h0, l0); split1(v[1], h1, l1);
                *(__half2*)(Ch + r0 * N + cc) = __half2(h0, h1);
                *(__half2*)(Cl + r0 * N + cc) = __half2(l0, l1);
                split1(v[2], h0, l0); split1(v[3], h1, l1);
                *(__half2*)(Ch + (r0 + 8) * N + cc) = __half2(h0, h1);
                *(__half2*)(Cl + (r0 + 8) * N + cc) = __half2(l0, l1);
            } else {
                *(float2*)(C + r0 * N + cc)       = make_float2(v[0], v[1]);
                *(float2*)(C + (r0 + 8) * N + cc) = make_float2(v[2], v[3]);
            }
        }
    }
}

// ---------------- PV GEMM: y = softmax(S) @ V ----------------
// 256 threads, 128x128 tile, occ 2. A-tile: S fp32 -> exp(s-m)*inv -> exact fp16 split.
// B: vT fp16 (rounded).
__global__ __launch_bounds__(256, 2)
void gemm_pv(const float* __restrict__ S, const float2* __restrict__ stat,
             const __half* __restrict__ Bh, float* __restrict__ C)
{
    extern __shared__ char sm[];
    const uint32_t smb = smem_to_u32(sm);
    const int tid  = threadIdx.x;
    const int wid  = tid >> 5;
    const int lane = tid & 31;

    S    += (long)blockIdx.z * TT * TT;
    stat += (long)blockIdx.z * TT;
    Bh   += (long)blockIdx.z * D_EMB * TT;
    C    += (long)blockIdx.z * TT * D_EMB;
    const int row0 = blockIdx.y * 128;
    const int col0 = blockIdx.x * 128;

    const int m0w = (wid & 3) * 32;
    const int n0w = (wid >> 2) * 64;

    float acc[2][8][4];
#pragma unroll
    for (int m = 0; m < 2; m++)
#pragma unroll
        for (int n = 0; n < 8; n++)
#pragma unroll
            for (int j = 0; j < 4; j++) acc[m][n][j] = 0.f;

    const uint32_t a_row = (uint32_t)((m0w + (lane & 15)) * TPITCH) + ((lane & 16) ? 16u : 0u);
    const uint32_t b_row = (uint32_t)((n0w + (lane & 7) + ((lane & 16) >> 1)) * TPITCH)
                         + ((lane & 8) ? 16u : 0u);

    for (int kt = 0; kt < TT / 64; kt++) {
        if (kt) __syncthreads();
        // A: S fp32 -> p = exp(s-m)*inv -> exact fp16 hi/lo split
#pragma unroll
        for (int i = 0; i < 4; i++) {
            int idx = tid + i * 256;
            int r  = idx >> 3;
            int ch = idx & 7;
            const float* p = S + (long)(row0 + r) * TT + kt * 64 + ch * 8;
            float2 st = stat[row0 + r];       // (m, inv)
            float4 f0 = *(const float4*)p;
            float4 f1 = *(const float4*)(p + 4);
            float f[8] = {f0.x, f0.y, f0.z, f0.w, f1.x, f1.y, f1.z, f1.w};
            unsigned int hi[4], lo[4];
#pragma unroll
            for (int j = 0; j < 4; j++) {
                float p0 = __expf(f[2*j]   - st.x) * st.y;
                float p1 = __expf(f[2*j+1] - st.x) * st.y;
                __half h0, l0, h1, l1;
                split1(p0, h0, l0); split1(p1, h1, l1);
                __half2 hh(h0, h1), ll(l0, l1);
                hi[j] = *(unsigned int*)&hh;
                lo[j] = *(unsigned int*)&ll;
            }
            uint32_t off = (uint32_t)(r * TPITCH + ch * 16);
            *(uint4*)(sm + off)      = make_uint4(hi[0], hi[1], hi[2], hi[3]);
            *(uint4*)(sm + TB + off) = make_uint4(lo[0], lo[1], lo[2], lo[3]);
        }
        // B: vT fp16 copy (rows = d in col0..col0+127)
        load_f16_tile(Bh + (long)col0 * TT + kt * 64, TT, sm, 2 * TB, tid);
        __syncthreads();

#pragma unroll
        for (int k16 = 0; k16 < 4; k16++) {
            const uint32_t kb = (uint32_t)(k16 * 32);
            uint32_t ah[2][4], al[2][4];
#pragma unroll
            for (int m = 0; m < 2; m++) {
                uint32_t aa = smb + a_row + (uint32_t)(m * 16 * TPITCH) + kb;
                LDMX4(ah[m][0], ah[m][1], ah[m][2], ah[m][3], aa);
                LDMX4(al[m][0], al[m][1], al[m][2], al[m][3], aa + TB);
            }
#pragma unroll
            for (int np = 0; np < 4; np++) {
                uint32_t ba = smb + 2 * TB + b_row + (uint32_t)(np * 16 * TPITCH) + kb;
                uint32_t bh[4];
                LDMX4(bh[0], bh[1], bh[2], bh[3], ba);
#pragma unroll
                for (int m = 0; m < 2; m++) {
                    MMA16816(acc[m][np*2],   ah[m], bh[0], bh[1]);
                    MMA16816(acc[m][np*2],   al[m], bh[0], bh[1]);
                    MMA16816(acc[m][np*2+1], ah[m], bh[2], bh[3]);
                    MMA16816(acc[m][np*2+1], al[m], bh[2], bh[3]);
                }
            }
        }
    }

#pragma unroll
    for (int m = 0; m < 2; m++) {
        const long r0 = row0 + m0w + m * 16 + (lane >> 2);
#pragma unroll
        for (int nb = 0; nb < 8; nb++) {
            const int cc = col0 + n0w + nb * 8 + (lane & 3) * 2;
            *(float2*)(C + r0 * D_EMB + cc)       = make_float2(acc[m][nb][0], acc[m][nb][1]);
            *(float2*)(C + (r0 + 8) * D_EMB + cc) = make_float2(acc[m][nb][2], acc[m][nb][3]);
        }
    }
}

// ---------------- row stats: (max, 1/sumexp) per S row ----------------
__device__ __forceinline__ float warp_red_max(float v) {
#pragma unroll
    for (int o = 16; o; o >>= 1) v = fmaxf(v, __shfl_xor_sync(0xffffffffu, v, o));
    return v;
}
__device__ __forceinline__ float warp_red_sum(float v) {
#pragma unroll
    for (int o = 16; o; o >>= 1) v += __shfl_xor_sync(0xffffffffu, v, o);
    return v;
}

__global__ __launch_bounds__(256)
void row_stats(const float* __restrict__ S, float2* __restrict__ stat)
{
    const long row = blockIdx.x;
    const float* p = S + row * TT;
    const int tid = threadIdx.x;
    __shared__ float red[8];

    float v[16];
#pragma unroll
    for (int j = 0; j < 16; j++) v[j] = p[tid + j * 256];

    float m = -3.4e38f;
#pragma unroll
    for (int j = 0; j < 16; j++) m = fmaxf(m, v[j]);
    m = warp_red_max(m);
    if ((tid & 31) == 0) red[tid >> 5] = m;
    __syncthreads();
    m = red[0];
#pragma unroll
    for (int i = 1; i < 8; i++) m = fmaxf(m, red[i]);
    __syncthreads();

    float s = 0.f;
#pragma unroll
    for (int j = 0; j < 16; j++) s += __expf(v[j] - m);
    s = warp_red_sum(s);
    if ((tid & 31) == 0) red[tid >> 5] = s;
    __syncthreads();
    if (tid == 0) {
        s = 0.f;
#pragma unroll
        for (int i = 0; i < 8; i++) s += red[i];
        stat[row] = make_float2(m, 1.f / s);
    }
}

// ---------------- elementwise split: fp32 -> fp16 hi/lo ----------------
__global__ __launch_bounds__(256)
void split2(const float* __restrict__ in, __half* __restrict__ oh,
            __half* __restrict__ ol)
{
    const long i = (long)blockIdx.x * 256 + threadIdx.x;
    float2 v = ((const float2*)in)[i];
    __half h0, l0, h1, l1;
    split1(v.x, h0, l0); split1(v.y, h1, l1);
    ((__half2*)oh)[i] = __half2(h0, h1);
    ((__half2*)ol)[i] = __half2(l0, l1);
}

// ---------------- tiled transpose + split ----------------
__global__ __launch_bounds__(256)
void transpose_split(const float* __restrict__ in,
                     __half* __restrict__ oh, __half* __restrict__ ol,
                     int rows, int cols, long sIn, long sOut)
{
    __shared__ float t[32][33];
    in += (long)blockIdx.z * sIn;
    oh += (long)blockIdx.z * sOut;  ol += (long)blockIdx.z * sOut;
    const int c0 = blockIdx.x * 32, r0 = blockIdx.y * 32;
    const int tx = threadIdx.x & 31, ty = threadIdx.x >> 5;
#pragma unroll
    for (int i = 0; i < 32; i += 8)
        t[ty + i][tx] = in[(long)(r0 + ty + i) * cols + c0 + tx];
    __syncthreads();
#pragma unroll
    for (int i = 0; i < 32; i += 8) {
        __half h, l;
        split1(t[tx][ty + i], h, l);
        const long o = (long)(c0 + ty + i) * rows + r0 + tx;
        oh[o] = h;  ol[o] = l;
    }
}

// ---------------- warp-per-row LayerNorm (D=256) ----------------
__device__ __forceinline__ void ln_row(const float* __restrict__ in,
                                       float v[8], int lane,
                                       const float* __restrict__ w,
                                       const float* __restrict__ b)
{
#pragma unroll
    for (int j = 0; j < 8; j++) v[j] = in[lane + j * 32];
    float s = 0.f;
#pragma unroll
    for (int j = 0; j < 8; j++) s += v[j];
    const float mean = warp_red_sum(s) * (1.f / 256.f);
    float q = 0.f;
#pragma unroll
    for (int j = 0; j < 8; j++) { float d = v[j] - mean; q += d * d; }
    const float rstd = rsqrtf(warp_red_sum(q) * (1.f / 256.f) + EPSLN);
#pragma unroll
    for (int j = 0; j < 8; j++) {
        const int e = lane + j * 32;
        v[j] = (v[j] - mean) * rstd * w[e] + b[e];
    }
}

__global__ __launch_bounds__(256)
void ln_qk(const float* __restrict__ wq, const float* __restrict__ bq,
           const float* __restrict__ wk, const float* __restrict__ bk,
           __half* __restrict__ qh, __half* __restrict__ ql,
           __half* __restrict__ kh, __half* __restrict__ kl)
{
    const int tensor = blockIdx.y;
    const float* base = g_qkv + (long)tensor * BT * D_EMB;
    const float* w = tensor ? wk : wq;
    const float* b = tensor ? bk : bq;
    __half* oh = tensor ? kh : qh;
    __half* ol = tensor ? kl : ql;
    const long row = (long)blockIdx.x * 8 + (threadIdx.x >> 5);
    const int lane = threadIdx.x & 31;
    float v[8];
    ln_row(base + row * D_EMB, v, lane, w, b);
#pragma unroll
    for (int j = 0; j < 8; j++) {
        __half h, l;
        split1(v[j], h, l);
        oh[row * D_EMB + lane + j * 32] = h;
        ol[row * D_EMB + lane + j * 32] = l;
    }
}

__global__ __launch_bounds__(256)
void attn_ln_res(const float* __restrict__ x,
                 const float* __restrict__ w, const float* __restrict__ b,
                 __half* __restrict__ oh, __half* __restrict__ ol)
{
    const long row = (long)blockIdx.x * 8 + (threadIdx.x >> 5);
    const int lane = threadIdx.x & 31;
    float v[8];
    ln_row(g_y + row * D_EMB, v, lane, w, b);
#pragma unroll
    for (int j = 0; j < 8; j++) {
        const long e = row * D_EMB + lane + j * 32;
        const float r = 0.7f * (x[e] + v[j]);
        g_x1[e] = r;
        __half h, l;
        split1(r, h, l);
        oh[e] = h;  ol[e] = l;
    }
}

__global__ __launch_bounds__(256)
void ff_ln_res(float* __restrict__ out,
               const float* __restrict__ w, const float* __restrict__ b)
{
    const long row = (long)blockIdx.x * 8 + (threadIdx.x >> 5);
    const int lane = threadIdx.x & 31;
    float v[8];
    ln_row(g_y2 + row * D_EMB, v, lane, w, b);
#pragma unroll
    for (int j = 0; j < 8; j++) {
        const long e = row * D_EMB + lane + j * 32;
        out[e] = 0.7f * (g_x1[e] + v[j]);
    }
}

// ---------------- launch ----------------
extern "C" void kernel_launch(void* const* d_in, const int* in_sizes, int n_in,
                              void* d_out, int out_size)
{
    const float* x      = (const float*)d_in[0];
    const float* qkvw   = (const float*)d_in[1];
    const float* ln_q_w = (const float*)d_in[2];
    const float* ln_q_b = (const float*)d_in[3];
    const float* ln_k_w = (const float*)d_in[4];
    const float* ln_k_b = (const float*)d_in[5];
    const float* ln_a_w = (const float*)d_in[6];
    const float* ln_a_b = (const float*)d_in[7];
    const float* w1     = (const float*)d_in[8];
    const float* w2     = (const float*)d_in[9];
    const float* ln_f_w = (const float*)d_in[10];
    const float* ln_f_b = (const float*)d_in[11];
    float* out = (float*)d_out;

    float *p_qkv, *p_scores, *p_y, *p_y2;
    float2* p_stat;
    __half *xs_h, *xs_l, *qts_h, *qts_l, *q_h, *q_l, *k_h, *k_l;
    __half *vts_h, *vts_l, *x1s_h, *x1s_l, *hs_h, *hs_l;
    __half *w1s_h, *w1s_l, *w2s_h, *w2s_l;
    cudaGetSymbolAddress((void**)&p_qkv,    g_qkv);
    cudaGetSymbolAddress((void**)&p_scores, g_scores);
    cudaGetSymbolAddress((void**)&p_stat,   g_stat);
    cudaGetSymbolAddress((void**)&p_y,      g_y);
    cudaGetSymbolAddress((void**)&p_y2,     g_y2);
    cudaGetSymbolAddress((void**)&xs_h,  g_xs_h);   cudaGetSymbolAddress((void**)&xs_l,  g_xs_l);
    cudaGetSymbolAddress((void**)&qts_h, g_qts_h);  cudaGetSymbolAddress((void**)&qts_l, g_qts_l);
    cudaGetSymbolAddress((void**)&q_h,   g_q_h);    cudaGetSymbolAddress((void**)&q_l,   g_q_l);
    cudaGetSymbolAddress((void**)&k_h,   g_k_h);    cudaGetSymbolAddress((void**)&k_l,   g_k_l);
    cudaGetSymbolAddress((void**)&vts_h, g_vts_h);  cudaGetSymbolAddress((void**)&vts_l, g_vts_l);
    cudaGetSymbolAddress((void**)&x1s_h, g_x1s_h);  cudaGetSymbolAddress((void**)&x1s_l, g_x1s_l);
    cudaGetSymbolAddress((void**)&hs_h,  g_hs_h);   cudaGetSymbolAddress((void**)&hs_l,  g_hs_l);
    cudaGetSymbolAddress((void**)&w1s_h, g_w1s_h);  cudaGetSymbolAddress((void**)&w1s_l, g_w1s_l);
    cudaGetSymbolAddress((void**)&w2s_h, g_w2s_h);  cudaGetSymbolAddress((void**)&w2s_l, g_w2s_l);

    cudaFuncSetAttribute(gemm_tc, cudaFuncAttributeMaxDynamicSharedMemorySize, GEMM_SMEM);
    cudaFuncSetAttribute(gemm_pv, cudaFuncAttributeMaxDynamicSharedMemorySize, GEMM_SMEM);

    // 0) input splits
    split2<<<BT * D_EMB / 512, 256>>>(x, xs_h, xs_l);
    split2<<<2 * D_EMB * D_EMB / 512, 256>>>(w1, w1s_h, w1s_l);
    split2<<<2 * D_EMB * D_EMB / 512, 256>>>(w2, w2s_h, w2s_l);
    transpose_split<<<dim3(8, 8, 3), 256>>>(qkvw, qts_h, qts_l, 256, 256,
                                            (long)D_EMB * D_EMB, (long)D_EMB * D_EMB);

    // 1) q,k,v = x @ qkvT^T (fp32 out)
    gemm_tc<<<dim3(2, 128, 3), 256, GEMM_SMEM>>>(
        xs_h, xs_l, qts_h, p_qkv, nullptr, nullptr,
        D_EMB, D_EMB, 0L, (long)D_EMB * D_EMB, (long)BT * D_EMB, 1.f, 0);

    // 2) vT split per batch
    transpose_split<<<dim3(8, 128, BB), 256>>>(p_qkv + 2L * BT * D_EMB, vts_h, vts_l,
                                               TT, D_EMB, (long)TT * D_EMB, (long)TT * D_EMB);

    // 3) LN(q), LN(k) -> splits
    ln_qk<<<dim3(BT / 8, 2), 256>>>(ln_q_w, ln_q_b, ln_k_w, ln_k_b, q_h, q_l, k_h, k_l);

    // 4) S = q @ k^T / 16   (A = q exact split, B = k fp16)
    gemm_tc<<<dim3(32, 32, BB), 256, GEMM_SMEM>>>(
        q_h, q_l, k_h, p_scores, nullptr, nullptr,
        D_EMB, TT, (long)TT * D_EMB, (long)TT * D_EMB, (long)TT * TT, 1.f / 16.f, 0);

    // 5) row stats (max, 1/sumexp)
    row_stats<<<BB * TT, 256>>>(p_scores, p_stat);

    // 6) y = softmax(S) @ V  (exp fused into A-tile load)
    gemm_pv<<<dim3(2, 32, BB), 256, GEMM_SMEM>>>(p_scores, p_stat, vts_h, p_y);

    // 7) x1 = 0.7*(x + LN(y)) -> fp32 + split
    attn_ln_res<<<BT / 8, 256>>>(x, ln_a_w, ln_a_b, x1s_h, x1s_l);

    // 8) h = leaky(x1 @ w1^T) -> fp16 split
    gemm_tc<<<dim3(4, 128, 1), 256, GEMM_SMEM>>>(
        x1s_h, x1s_l, w1s_h, nullptr, hs_h, hs_l,
        D_EMB, 2 * D_EMB, 0L, 0L, 0L, 1.f, 2);

    // 9) y2 = leaky(h @ w2^T) (fp32 out)
    gemm_tc<<<dim3(2, 128, 1), 256, GEMM_SMEM>>>(
        hs_h, hs_l, w2s_h, p_y2, nullptr, nullptr,
        2 * D_EMB, D_EMB, 0L, 0L, 0L, 1.f, 1);

    // 10) out = 0.7 * (x1 + LN(y2))
    ff_ln_res<<<BT / 8, 256>>>(out, ln_f_w, ln_f_b);
}

// round 17
// speedup vs baseline: 1.5437x; 1.0923x over previous
#include <cuda_runtime.h>
#include <cuda_fp16.h>
#include <math.h>
#include <stdint.h>

#define D_EMB 256
#define TT    4096
#define BB    4
#define BT    (BB*TT)          // 16384 rows
#define EPSLN 1e-5f

// ---------------- scratch (static device globals: allocation-free) ----------------
__device__ float  g_qkv[3L * BT * D_EMB];            // q,k,v fp32
__device__ float  g_scores[(long)BB * TT * TT];      // scaled scores S
__device__ float2 g_stat[(long)BB * TT];             // (rowmax, 1/sumexp)
__device__ float  g_y [BT * D_EMB];                  // attn out
__device__ float  g_x1[BT * D_EMB];                  // post-attn residual
__device__ float  g_y2[BT * D_EMB];                  // ffn out

// fp16 hi/lo split operands (lo used only on A-side of each GEMM)
__device__ __half g_xs_h [BT * D_EMB],        g_xs_l [BT * D_EMB];
__device__ __half g_qts_h[3 * D_EMB * D_EMB], g_qts_l[3 * D_EMB * D_EMB];
__device__ __half g_q_h  [BT * D_EMB],        g_q_l  [BT * D_EMB];
__device__ __half g_k_h  [BT * D_EMB],        g_k_l  [BT * D_EMB];
__device__ __half g_vts_h[BT * D_EMB],        g_vts_l[BT * D_EMB];
__device__ __half g_x1s_h[BT * D_EMB],        g_x1s_l[BT * D_EMB];
__device__ __half g_hs_h [BT * 2 * D_EMB],    g_hs_l [BT * 2 * D_EMB];
__device__ __half g_w1s_h[2 * D_EMB * D_EMB], g_w1s_l[2 * D_EMB * D_EMB];
__device__ __half g_w2s_h[2 * D_EMB * D_EMB], g_w2s_l[2 * D_EMB * D_EMB];

// ================= helpers (baseline PTX, no 'a' features) =================
__device__ __forceinline__ uint32_t smem_to_u32(const void* p) {
    uint32_t a;
    asm("{ .reg .u64 t; cvta.to.shared.u64 t, %1; cvt.u32.u64 %0, t; }" : "=r"(a) : "l"(p));
    return a;
}
#define LDMX4(r0, r1, r2, r3, addr) \
    asm volatile("ldmatrix.sync.aligned.m8n8.x4.shared.b16 {%0,%1,%2,%3}, [%4];" \
        : "=r"(r0), "=r"(r1), "=r"(r2), "=r"(r3) : "r"(addr))
#define MMA16816(c, a, b0v, b1v) \
    asm volatile("mma.sync.aligned.m16n8k16.row.col.f32.f16.f16.f32 " \
        "{%0,%1,%2,%3}, {%4,%5,%6,%7}, {%8,%9}, {%0,%1,%2,%3};" \
        : "+f"((c)[0]), "+f"((c)[1]), "+f"((c)[2]), "+f"((c)[3]) \
        : "r"((a)[0]), "r"((a)[1]), "r"((a)[2]), "r"((a)[3]), "r"(b0v), "r"(b1v))

// exact fp16 split: v == (float)h + (float)l to ~22 bits
__device__ __forceinline__ void split1(float v, __half& h, __half& l) {
    h = __float2half_rn(v);
    l = __float2half_rn(v - __half2float(h));
}

// smem tile: 128 rows x 64 fp16, row pitch 144 B (proven ldmatrix layout)
#define TPITCH 144
#define TB     (128 * TPITCH)        // 18432
#define GEMM_SMEM (3 * TB)           // AH, AL, BH: 55296
#define PV_SMEM   (2 * TB)           // AH, BH: 36864

// copy one 128x64 fp16 tile (pre-split source) into smem; 256 threads
__device__ __forceinline__ void load_f16_tile(const __half* __restrict__ g, int ld,
                                              char* sm, int off, int tid)
{
#pragma unroll
    for (int i = 0; i < 4; i++) {
        int idx = tid + i * 256;
        int r  = idx >> 3;
        int ch = idx & 7;
        *(uint4*)(sm + off + r * TPITCH + ch * 16) =
            *(const uint4*)(g + (long)r * ld + ch * 8);
    }
}

// ---------------- 256-thread GEMM: 2-product fp16 emulation ----------------
// C[M,N] = epi(alpha * (Ah+Al)[M,K] @ Bh[N,K]^T)
// epi: 0 none (fp32 C), 1 leaky (fp32 C), 2 leaky + fp16 split out (Ch, Cl)
__global__ __launch_bounds__(256, 2)
void gemm_tc(const __half* __restrict__ Ah, const __half* __restrict__ Al,
             const __half* __restrict__ Bh,
             float* __restrict__ C, __half* __restrict__ Ch, __half* __restrict__ Cl,
             int K, int N, long sA, long sB, long sC, float alpha, int epi)
{
    extern __shared__ char sm[];
    const uint32_t smb = smem_to_u32(sm);
    const int tid  = threadIdx.x;
    const int wid  = tid >> 5;
    const int lane = tid & 31;

    Ah += blockIdx.z * sA;  Al += blockIdx.z * sA;
    Bh += blockIdx.z * sB;
    const int row0 = blockIdx.y * 128;
    const int col0 = blockIdx.x * 128;

    const int m0w = (wid & 3) * 32;
    const int n0w = (wid >> 2) * 64;

    float acc[2][8][4];
#pragma unroll
    for (int m = 0; m < 2; m++)
#pragma unroll
        for (int n = 0; n < 8; n++)
#pragma unroll
            for (int j = 0; j < 4; j++) acc[m][n][j] = 0.f;

    const uint32_t a_row = (uint32_t)((m0w + (lane & 15)) * TPITCH) + ((lane & 16) ? 16u : 0u);
    const uint32_t b_row = (uint32_t)((n0w + (lane & 7) + ((lane & 16) >> 1)) * TPITCH)
                         + ((lane & 8) ? 16u : 0u);

    const int KT = K >> 6;
    for (int kt = 0; kt < KT; kt++) {
        if (kt) __syncthreads();
        const long ko = (long)kt * 64;
        load_f16_tile(Ah + (long)row0 * K + ko, K, sm, 0,      tid);
        load_f16_tile(Al + (long)row0 * K + ko, K, sm, TB,     tid);
        load_f16_tile(Bh + (long)col0 * K + ko, K, sm, 2 * TB, tid);
        __syncthreads();

#pragma unroll
        for (int k16 = 0; k16 < 4; k16++) {
            const uint32_t kb = (uint32_t)(k16 * 32);
            uint32_t ah[2][4], al[2][4];
#pragma unroll
            for (int m = 0; m < 2; m++) {
                uint32_t aa = smb + a_row + (uint32_t)(m * 16 * TPITCH) + kb;
                LDMX4(ah[m][0], ah[m][1], ah[m][2], ah[m][3], aa);
                LDMX4(al[m][0], al[m][1], al[m][2], al[m][3], aa + TB);
            }
#pragma unroll
            for (int np = 0; np < 4; np++) {
                uint32_t ba = smb + 2 * TB + b_row + (uint32_t)(np * 16 * TPITCH) + kb;
                uint32_t bh[4];
                LDMX4(bh[0], bh[1], bh[2], bh[3], ba);
#pragma unroll
                for (int m = 0; m < 2; m++) {
                    MMA16816(acc[m][np*2],   ah[m], bh[0], bh[1]);
                    MMA16816(acc[m][np*2],   al[m], bh[0], bh[1]);
                    MMA16816(acc[m][np*2+1], ah[m], bh[2], bh[3]);
                    MMA16816(acc[m][np*2+1], al[m], bh[2], bh[3]);
                }
            }
        }
    }

    C  += blockIdx.z * sC;
    Ch += blockIdx.z * sC;  Cl += blockIdx.z * sC;
#pragma unroll
    for (int m = 0; m < 2; m++) {
        const long r0 = row0 + m0w + m * 16 + (lane >> 2);
#pragma unroll
        for (int nb = 0; nb < 8; nb++) {
            const int cc = col0 + n0w + nb * 8 + (lane & 3) * 2;
            float v[4];
            v[0] = alpha * acc[m][nb][0];  v[1] = alpha * acc[m][nb][1];
            v[2] = alpha * acc[m][nb][2];  v[3] = alpha * acc[m][nb][3];
            if (epi >= 1) {
#pragma unroll
                for (int j = 0; j < 4; j++) v[j] = v[j] > 0.f ? v[j] : 0.2f * v[j];
            }
            if (epi == 2) {
                __half h0, l0, h1, l1;
                split1(v[0], h0, l0); split1(v[1], h1, l1);
                *(__half2*)(Ch + r0 * N + cc) = __half2(h0, h1);
                *(__half2*)(Cl + r0 * N + cc) = __half2(l0, l1);
                split1(v[2], h0, l0); split1(v[3], h1, l1);
                *(__half2*)(Ch + (r0 + 8) * N + cc) = __half2(h0, h1);
                *(__half2*)(Cl + (r0 + 8) * N + cc) = __half2(l0, l1);
            } else {
                *(float2*)(C + r0 * N + cc)       = make_float2(v[0], v[1]);
                *(float2*)(C + (r0 + 8) * N + cc) = make_float2(v[2], v[3]);
            }
        }
    }
}

// ---------------- PV GEMM: y = softmax(S) @ V, single-product P ----------------
// 256 threads, 128x128 tile, occ 2. A-tile: S fp32 -> exp(s-m)*inv -> single fp16.
// B: vT fp16 (rounded). P in [0,1]: single rounding adds ~5e-4 relative on y.
__global__ __launch_bounds__(256, 2)
void gemm_pv(const float* __restrict__ S, const float2* __restrict__ stat,
             const __half* __restrict__ Bh, float* __restrict__ C)
{
    extern __shared__ char sm[];
    const uint32_t smb = smem_to_u32(sm);
    const int tid  = threadIdx.x;
    const int wid  = tid >> 5;
    const int lane = tid & 31;

    S    += (long)blockIdx.z * TT * TT;
    stat += (long)blockIdx.z * TT;
    Bh   += (long)blockIdx.z * D_EMB * TT;
    C    += (long)blockIdx.z * TT * D_EMB;
    const int row0 = blockIdx.y * 128;
    const int col0 = blockIdx.x * 128;

    const int m0w = (wid & 3) * 32;
    const int n0w = (wid >> 2) * 64;

    float acc[2][8][4];
#pragma unroll
    for (int m = 0; m < 2; m++)
#pragma unroll
        for (int n = 0; n < 8; n++)
#pragma unroll
            for (int j = 0; j < 4; j++) acc[m][n][j] = 0.f;

    const uint32_t a_row = (uint32_t)((m0w + (lane & 15)) * TPITCH) + ((lane & 16) ? 16u : 0u);
    const uint32_t b_row = (uint32_t)((n0w + (lane & 7) + ((lane & 16) >> 1)) * TPITCH)
                         + ((lane & 8) ? 16u : 0u);

    for (int kt = 0; kt < TT / 64; kt++) {
        if (kt) __syncthreads();
        // A: S fp32 -> p = exp(s-m)*inv -> fp16 (single product)
#pragma unroll
        for (int i = 0; i < 4; i++) {
            int idx = tid + i * 256;
            int r  = idx >> 3;
            int ch = idx & 7;
            const float* p = S + (long)(row0 + r) * TT + kt * 64 + ch * 8;
            float2 st = stat[row0 + r];       // (m, inv)
            float4 f0 = *(const float4*)p;
            float4 f1 = *(const float4*)(p + 4);
            float f[8] = {f0.x, f0.y, f0.z, f0.w, f1.x, f1.y, f1.z, f1.w};
            unsigned int hi[4];
#pragma unroll
            for (int j = 0; j < 4; j++) {
                float p0 = __expf(f[2*j]   - st.x) * st.y;
                float p1 = __expf(f[2*j+1] - st.x) * st.y;
                __half2 hh(__float2half_rn(p0), __float2half_rn(p1));
                hi[j] = *(unsigned int*)&hh;
            }
            uint32_t off = (uint32_t)(r * TPITCH + ch * 16);
            *(uint4*)(sm + off) = make_uint4(hi[0], hi[1], hi[2], hi[3]);
        }
        // B: vT fp16 copy (rows = d in col0..col0+127)
        load_f16_tile(Bh + (long)col0 * TT + kt * 64, TT, sm, TB, tid);
        __syncthreads();

#pragma unroll
        for (int k16 = 0; k16 < 4; k16++) {
            const uint32_t kb = (uint32_t)(k16 * 32);
            uint32_t ah[2][4];
#pragma unroll
            for (int m = 0; m < 2; m++) {
                uint32_t aa = smb + a_row + (uint32_t)(m * 16 * TPITCH) + kb;
                LDMX4(ah[m][0], ah[m][1], ah[m][2], ah[m][3], aa);
            }
#pragma unroll
            for (int np = 0; np < 4; np++) {
                uint32_t ba = smb + TB + b_row + (uint32_t)(np * 16 * TPITCH) + kb;
                uint32_t bh[4];
                LDMX4(bh[0], bh[1], bh[2], bh[3], ba);
#pragma unroll
                for (int m = 0; m < 2; m++) {
                    MMA16816(acc[m][np*2],   ah[m], bh[0], bh[1]);
                    MMA16816(acc[m][np*2+1], ah[m], bh[2], bh[3]);
                }
            }
        }
    }

#pragma unroll
    for (int m = 0; m < 2; m++) {
        const long r0 = row0 + m0w + m * 16 + (lane >> 2);
#pragma unroll
        for (int nb = 0; nb < 8; nb++) {
            const int cc = col0 + n0w + nb * 8 + (lane & 3) * 2;
            *(float2*)(C + r0 * D_EMB + cc)       = make_float2(acc[m][nb][0], acc[m][nb][1]);
            *(float2*)(C + (r0 + 8) * D_EMB + cc) = make_float2(acc[m][nb][2], acc[m][nb][3]);
        }
    }
}

// ---------------- row stats: (max, 1/sumexp) per S row ----------------
__device__ __forceinline__ float warp_red_max(float v) {
#pragma unroll
    for (int o = 16; o; o >>= 1) v = fmaxf(v, __shfl_xor_sync(0xffffffffu, v, o));
    return v;
}
__device__ __forceinline__ float warp_red_sum(float v) {
#pragma unroll
    for (int o = 16; o; o >>= 1) v += __shfl_xor_sync(0xffffffffu, v, o);
    return v;
}

__global__ __launch_bounds__(256)
void row_stats(const float* __restrict__ S, float2* __restrict__ stat)
{
    const long row = blockIdx.x;
    const float* p = S + row * TT;
    const int tid = threadIdx.x;
    __shared__ float red[8];

    float v[16];
#pragma unroll
    for (int j = 0; j < 16; j++) v[j] = p[tid + j * 256];

    float m = -3.4e38f;
#pragma unroll
    for (int j = 0; j < 16; j++) m = fmaxf(m, v[j]);
    m = warp_red_max(m);
    if ((tid & 31) == 0) red[tid >> 5] = m;
    __syncthreads();
    m = red[0];
#pragma unroll
    for (int i = 1; i < 8; i++) m = fmaxf(m, red[i]);
    __syncthreads();

    float s = 0.f;
#pragma unroll
    for (int j = 0; j < 16; j++) s += __expf(v[j] - m);
    s = warp_red_sum(s);
    if ((tid & 31) == 0) red[tid >> 5] = s;
    __syncthreads();
    if (tid == 0) {
        s = 0.f;
#pragma unroll
        for (int i = 0; i < 8; i++) s += red[i];
        stat[row] = make_float2(m, 1.f / s);
    }
}

// ---------------- elementwise split: fp32 -> fp16 hi/lo ----------------
__global__ __launch_bounds__(256)
void split2(const float* __restrict__ in, __half* __restrict__ oh,
            __half* __restrict__ ol)
{
    const long i = (long)blockIdx.x * 256 + threadIdx.x;
    float2 v = ((const float2*)in)[i];
    __half h0, l0, h1, l1;
    split1(v.x, h0, l0); split1(v.y, h1, l1);
    ((__half2*)oh)[i] = __half2(h0, h1);
    ((__half2*)ol)[i] = __half2(l0, l1);
}

// ---------------- tiled transpose + split ----------------
__global__ __launch_bounds__(256)
void transpose_split(const float* __restrict__ in,
                     __half* __restrict__ oh, __half* __restrict__ ol,
                     int rows, int cols, long sIn, long sOut)
{
    __shared__ float t[32][33];
    in += (long)blockIdx.z * sIn;
    oh += (long)blockIdx.z * sOut;  ol += (long)blockIdx.z * sOut;
    const int c0 = blockIdx.x * 32, r0 = blockIdx.y * 32;
    const int tx = threadIdx.x & 31, ty = threadIdx.x >> 5;
#pragma unroll
    for (int i = 0; i < 32; i += 8)
        t[ty + i][tx] = in[(long)(r0 + ty + i) * cols + c0 + tx];
    __syncthreads();
#pragma unroll
    for (int i = 0; i < 32; i += 8) {
        __half h, l;
        split1(t[tx][ty + i], h, l);
        const long o = (long)(c0 + ty + i) * rows + r0 + tx;
        oh[o] = h;  ol[o] = l;
    }
}

// ---------------- warp-per-row LayerNorm (D=256) ----------------
__device__ __forceinline__ void ln_row(const float* __restrict__ in,
                                       float v[8], int lane,
                                       const float* __restrict__ w,
                                       const float* __restrict__ b)
{
#pragma unroll
    for (int j = 0; j < 8; j++) v[j] = in[lane + j * 32];
    float s = 0.f;
#pragma unroll
    for (int j = 0; j < 8; j++) s += v[j];
    const float mean = warp_red_sum(s) * (1.f / 256.f);
    float q = 0.f;
#pragma unroll
    for (int j = 0; j < 8; j++) { float d = v[j] - mean; q += d * d; }
    const float rstd = rsqrtf(warp_red_sum(q) * (1.f / 256.f) + EPSLN);
#pragma unroll
    for (int j = 0; j < 8; j++) {
        const int e = lane + j * 32;
        v[j] = (v[j] - mean) * rstd * w[e] + b[e];
    }
}

__global__ __launch_bounds__(256)
void ln_qk(const float* __restrict__ wq, const float* __restrict__ bq,
           const float* __restrict__ wk, const float* __restrict__ bk,
           __half* __restrict__ qh, __half* __restrict__ ql,
           __half* __restrict__ kh, __half* __restrict__ kl)
{
    const int tensor = blockIdx.y;
    const float* base = g_qkv + (long)tensor * BT * D_EMB;
    const float* w = tensor ? wk : wq;
    const float* b = tensor ? bk : bq;
    __half* oh = tensor ? kh : qh;
    __half* ol = tensor ? kl : ql;
    const long row = (long)blockIdx.x * 8 + (threadIdx.x >> 5);
    const int lane = threadIdx.x & 31;
    float v[8];
    ln_row(base + row * D_EMB, v, lane, w, b);
#pragma unroll
    for (int j = 0; j < 8; j++) {
        __half h, l;
        split1(v[j], h, l);
        oh[row * D_EMB + lane + j * 32] = h;
        ol[row * D_EMB + lane + j * 32] = l;
    }
}

__global__ __launch_bounds__(256)
void attn_ln_res(const float* __restrict__ x,
                 const float* __restrict__ w, const float* __restrict__ b,
                 __half* __restrict__ oh, __half* __restrict__ ol)
{
    const long row = (long)blockIdx.x * 8 + (threadIdx.x >> 5);
    const int lane = threadIdx.x & 31;
    float v[8];
    ln_row(g_y + row * D_EMB, v, lane, w, b);
#pragma unroll
    for (int j = 0; j < 8; j++) {
        const long e = row * D_EMB + lane + j * 32;
        const float r = 0.7f * (x[e] + v[j]);
        g_x1[e] = r;
        __half h, l;
        split1(r, h, l);
        oh[e] = h;  ol[e] = l;
    }
}

__global__ __launch_bounds__(256)
void ff_ln_res(float* __restrict__ out,
               const float* __restrict__ w, const float* __restrict__ b)
{
    const long row = (long)blockIdx.x * 8 + (threadIdx.x >> 5);
    const int lane = threadIdx.x & 31;
    float v[8];
    ln_row(g_y2 + row * D_EMB, v, lane, w, b);
#pragma unroll
    for (int j = 0; j < 8; j++) {
        const long e = row * D_EMB + lane + j * 32;
        out[e] = 0.7f * (g_x1[e] + v[j]);
    }
}

// ---------------- launch ----------------
extern "C" void kernel_launch(void* const* d_in, const int* in_sizes, int n_in,
                              void* d_out, int out_size)
{
    const float* x      = (const float*)d_in[0];
    const float* qkvw   = (const float*)d_in[1];
    const float* ln_q_w = (const float*)d_in[2];
    const float* ln_q_b = (const float*)d_in[3];
    const float* ln_k_w = (const float*)d_in[4];
    const float* ln_k_b = (const float*)d_in[5];
    const float* ln_a_w = (const float*)d_in[6];
    const float* ln_a_b = (const float*)d_in[7];
    const float* w1     = (const float*)d_in[8];
    const float* w2     = (const float*)d_in[9];
    const float* ln_f_w = (const float*)d_in[10];
    const float* ln_f_b = (const float*)d_in[11];
    float* out = (float*)d_out;

    float *p_qkv, *p_scores, *p_y, *p_y2;
    float2* p_stat;
    __half *xs_h, *xs_l, *qts_h, *qts_l, *q_h, *q_l, *k_h, *k_l;
    __half *vts_h, *vts_l, *x1s_h, *x1s_l, *hs_h, *hs_l;
    __half *w1s_h, *w1s_l, *w2s_h, *w2s_l;
    cudaGetSymbolAddress((void**)&p_qkv,    g_qkv);
    cudaGetSymbolAddress((void**)&p_scores, g_scores);
    cudaGetSymbolAddress((void**)&p_stat,   g_stat);
    cudaGetSymbolAddress((void**)&p_y,      g_y);
    cudaGetSymbolAddress((void**)&p_y2,     g_y2);
    cudaGetSymbolAddress((void**)&xs_h,  g_xs_h);   cudaGetSymbolAddress((void**)&xs_l,  g_xs_l);
    cudaGetSymbolAddress((void**)&qts_h, g_qts_h);  cudaGetSymbolAddress((void**)&qts_l, g_qts_l);
    cudaGetSymbolAddress((void**)&q_h,   g_q_h);    cudaGetSymbolAddress((void**)&q_l,   g_q_l);
    cudaGetSymbolAddress((void**)&k_h,   g_k_h);    cudaGetSymbolAddress((void**)&k_l,   g_k_l);
    cudaGetSymbolAddress((void**)&vts_h, g_vts_h);  cudaGetSymbolAddress((void**)&vts_l, g_vts_l);
    cudaGetSymbolAddress((void**)&x1s_h, g_x1s_h);  cudaGetSymbolAddress((void**)&x1s_l, g_x1s_l);
    cudaGetSymbolAddress((void**)&hs_h,  g_hs_h);   cudaGetSymbolAddress((void**)&hs_l,  g_hs_l);
    cudaGetSymbolAddress((void**)&w1s_h, g_w1s_h);  cudaGetSymbolAddress((void**)&w1s_l, g_w1s_l);
    cudaGetSymbolAddress((void**)&w2s_h, g_w2s_h);  cudaGetSymbolAddress((void**)&w2s_l, g_w2s_l);

    cudaFuncSetAttribute(gemm_tc, cudaFuncAttributeMaxDynamicSharedMemorySize, GEMM_SMEM);
    cudaFuncSetAttribute(gemm_pv, cudaFuncAttributeMaxDynamicSharedMemorySize, PV_SMEM);

    // 0) input splits
    split2<<<BT * D_EMB / 512, 256>>>(x, xs_h, xs_l);
    split2<<<2 * D_EMB * D_EMB / 512, 256>>>(w1, w1s_h, w1s_l);
    split2<<<2 * D_EMB * D_EMB / 512, 256>>>(w2, w2s_h, w2s_l);
    transpose_split<<<dim3(8, 8, 3), 256>>>(qkvw, qts_h, qts_l, 256, 256,
                                            (long)D_EMB * D_EMB, (long)D_EMB * D_EMB);

    // 1) q,k,v = x @ qkvT^T (fp32 out)
    gemm_tc<<<dim3(2, 128, 3), 256, GEMM_SMEM>>>(
        xs_h, xs_l, qts_h, p_qkv, nullptr, nullptr,
        D_EMB, D_EMB, 0L, (long)D_EMB * D_EMB, (long)BT * D_EMB, 1.f, 0);

    // 2) vT split per batch
    transpose_split<<<dim3(8, 128, BB), 256>>>(p_qkv + 2L * BT * D_EMB, vts_h, vts_l,
                                               TT, D_EMB, (long)TT * D_EMB, (long)TT * D_EMB);

    // 3) LN(q), LN(k) -> splits
    ln_qk<<<dim3(BT / 8, 2), 256>>>(ln_q_w, ln_q_b, ln_k_w, ln_k_b, q_h, q_l, k_h, k_l);

    // 4) S = q @ k^T / 16   (A = q exact split, B = k fp16)
    gemm_tc<<<dim3(32, 32, BB), 256, GEMM_SMEM>>>(
        q_h, q_l, k_h, p_scores, nullptr, nullptr,
        D_EMB, TT, (long)TT * D_EMB, (long)TT * D_EMB, (long)TT * TT, 1.f / 16.f, 0);

    // 5) row stats (max, 1/sumexp)
    row_stats<<<BB * TT, 256>>>(p_scores, p_stat);

    // 6) y = softmax(S) @ V  (exp fused; single-product P)
    gemm_pv<<<dim3(2, 32, BB), 256, PV_SMEM>>>(p_scores, p_stat, vts_h, p_y);

    // 7) x1 = 0.7*(x + LN(y)) -> fp32 + split
    attn_ln_res<<<BT / 8, 256>>>(x, ln_a_w, ln_a_b, x1s_h, x1s_l);

    // 8) h = leaky(x1 @ w1^T) -> fp16 split
    gemm_tc<<<dim3(4, 128, 1), 256, GEMM_SMEM>>>(
        x1s_h, x1s_l, w1s_h, nullptr, hs_h, hs_l,
        D_EMB, 2 * D_EMB, 0L, 0L, 0L, 1.f, 2);

    // 9) y2 = leaky(h @ w2^T) (fp32 out)
    gemm_tc<<<dim3(2, 128, 1), 256, GEMM_SMEM>>>(
        hs_h, hs_l, w2s_h, p_y2, nullptr, nullptr,
        2 * D_EMB, D_EMB, 0L, 0L, 0L, 1.f, 1);

    // 10) out = 0.7 * (x1 + LN(y2))
    ff_ln_res<<<BT / 8, 256>>>(out, ln_f_w, ln_f_b);
}